// round 3
// baseline (speedup 1.0000x reference)
#include <cuda_runtime.h>
#include <math.h>
#include <stdint.h>

#define LSEQ 256
#define VEC  256
#define HID  256
#define NR1  96      // 32 question seqs + 64 article seqs
#define NR2  64      // Beff rows
#define LD   512     // 2*HID
#define F8   2048

// ------------------- scratch (device globals; no allocs) -------------------
__device__ float g_X1 [LSEQ*NR1*VEC];        // [t][row][v]
__device__ float g_GI1[LSEQ*1536*NR1];       // [t][d*768+g*256+u][row]
__device__ float g_HS1[LSEQ*2*HID*NR1];      // [t][d][u][row]
__device__ float g_CQ1[NR1*LSEQ*LD];         // [seq][t][d]
__device__ float g_CW2[NR2*LSEQ*LD];         // [r][i][d]  (c * w2)
__device__ float g_S  [NR2*LSEQ*LSEQ];       // scores then probs
__device__ float g_CW [NR2*LSEQ];
__device__ float g_QW [NR2*LSEQ];
__device__ float g_M  [NR2*LSEQ];            // row max of scores
__device__ float g_Q2C[NR2*LD];
__device__ float g_C2Q[NR2*LSEQ*LD];         // [r][i][d]
__device__ float g_ATT[LSEQ*NR2*F8];         // [i][r][f]
__device__ float g_GI2[LSEQ*1536*NR2];
__device__ float g_HS2[LSEQ*2*HID*NR2];
__device__ float g_C2 [NR2*LSEQ*LD];
__device__ float g_AT2[LSEQ*NR2*F8];

// ------------------- embedding gather -------------------
__global__ void k_embed(const int* __restrict__ q, const int* __restrict__ a,
                        const float* __restrict__ emb)
{
    int t = blockIdx.x, r = blockIdx.y;
    int tok = (r < 32) ? q[r*LSEQ + t] : a[(r-32)*LSEQ + t];
    const float4* src = (const float4*)(emb + (size_t)tok*VEC);
    float4* dst = (float4*)(g_X1 + ((size_t)t*NR1 + r)*VEC);
    dst[threadIdx.x] = src[threadIdx.x];
}

// ------------------- GEMM NT: C[m][n] = sum_k A[m][k]*B[n][k] (+bias[m]) ---
// BM=BN=64, BK=16, 128 threads, 8x4 micro-tile. M%64==0, K%16==0; N guarded.
__global__ void k_gemm_nt(const float* __restrict__ A, const float* __restrict__ B,
                          float* __restrict__ C, const float* __restrict__ bias,
                          int M, int N, int K, long sA, long sB, long sC)
{
    const float* Ab = A + (size_t)blockIdx.z * sA;
    const float* Bb = B + (size_t)blockIdx.z * sB;
    float* Cb = C + (size_t)blockIdx.z * sC;
    int m0 = blockIdx.x * 64, n0 = blockIdx.y * 64;
    int tid = threadIdx.x;
    int tn = tid & 15, tm = tid >> 4;
    __shared__ float As[16][68];
    __shared__ float Bs[16][68];
    float acc[8][4];
#pragma unroll
    for (int i = 0; i < 8; i++)
#pragma unroll
        for (int j = 0; j < 4; j++) acc[i][j] = 0.f;

    for (int k0 = 0; k0 < K; k0 += 16) {
#pragma unroll
        for (int it = 0; it < 2; it++) {
            int idx = tid + it*128;
            int row = idx >> 2, c4 = idx & 3;
            float4 v = *(const float4*)(Ab + (size_t)(m0+row)*K + k0 + c4*4);
            As[c4*4+0][row]=v.x; As[c4*4+1][row]=v.y; As[c4*4+2][row]=v.z; As[c4*4+3][row]=v.w;
        }
#pragma unroll
        for (int it = 0; it < 2; it++) {
            int idx = tid + it*128;
            int row = idx >> 2, c4 = idx & 3;
            float4 v = make_float4(0.f,0.f,0.f,0.f);
            if (n0 + row < N) v = *(const float4*)(Bb + (size_t)(n0+row)*K + k0 + c4*4);
            Bs[c4*4+0][row]=v.x; Bs[c4*4+1][row]=v.y; Bs[c4*4+2][row]=v.z; Bs[c4*4+3][row]=v.w;
        }
        __syncthreads();
#pragma unroll
        for (int kk = 0; kk < 16; kk++) {
            float a[8], b[4];
            *(float4*)(a)   = *(const float4*)&As[kk][tm*8];
            *(float4*)(a+4) = *(const float4*)&As[kk][tm*8+4];
            *(float4*)(b)   = *(const float4*)&Bs[kk][tn*4];
#pragma unroll
            for (int i = 0; i < 8; i++)
#pragma unroll
                for (int j = 0; j < 4; j++) acc[i][j] = fmaf(a[i], b[j], acc[i][j]);
        }
        __syncthreads();
    }
#pragma unroll
    for (int i = 0; i < 8; i++) {
        int m = m0 + tm*8 + i;
        float bi = bias ? bias[m] : 0.f;
#pragma unroll
        for (int j = 0; j < 4; j++) {
            int n = n0 + tn*4 + j;
            if (n < N) Cb[(size_t)m*N + n] = acc[i][j] + bi;
        }
    }
}

// ------------------- GEMM NN: C[m][n] = sum_k A[m][k]*B[k][n] --------------
// M%64==0, N%64==0, K%16==0 (no guards needed for our shapes).
__global__ void k_gemm_nn(const float* __restrict__ A, const float* __restrict__ B,
                          float* __restrict__ C,
                          int M, int N, int K, long sA, long sB, long sC)
{
    const float* Ab = A + (size_t)blockIdx.z * sA;
    const float* Bb = B + (size_t)blockIdx.z * sB;
    float* Cb = C + (size_t)blockIdx.z * sC;
    int m0 = blockIdx.x * 64, n0 = blockIdx.y * 64;
    int tid = threadIdx.x;
    int tn = tid & 15, tm = tid >> 4;
    __shared__ float As[16][68];
    __shared__ float Bs[16][68];
    float acc[8][4];
#pragma unroll
    for (int i = 0; i < 8; i++)
#pragma unroll
        for (int j = 0; j < 4; j++) acc[i][j] = 0.f;

    for (int k0 = 0; k0 < K; k0 += 16) {
#pragma unroll
        for (int it = 0; it < 2; it++) {
            int idx = tid + it*128;
            int row = idx >> 2, c4 = idx & 3;
            float4 v = *(const float4*)(Ab + (size_t)(m0+row)*K + k0 + c4*4);
            As[c4*4+0][row]=v.x; As[c4*4+1][row]=v.y; As[c4*4+2][row]=v.z; As[c4*4+3][row]=v.w;
        }
#pragma unroll
        for (int it = 0; it < 2; it++) {
            int idx = tid + it*128;
            int row = idx >> 4, c4 = idx & 15;
            float4 v = *(const float4*)(Bb + (size_t)(k0+row)*N + n0 + c4*4);
            *(float4*)&Bs[row][c4*4] = v;
        }
        __syncthreads();
#pragma unroll
        for (int kk = 0; kk < 16; kk++) {
            float a[8], b[4];
            *(float4*)(a)   = *(const float4*)&As[kk][tm*8];
            *(float4*)(a+4) = *(const float4*)&As[kk][tm*8+4];
            *(float4*)(b)   = *(const float4*)&Bs[kk][tn*4];
#pragma unroll
            for (int i = 0; i < 8; i++)
#pragma unroll
                for (int j = 0; j < 4; j++) acc[i][j] = fmaf(a[i], b[j], acc[i][j]);
        }
        __syncthreads();
    }
#pragma unroll
    for (int i = 0; i < 8; i++) {
        int m = m0 + tm*8 + i;
#pragma unroll
        for (int j = 0; j < 4; j++)
            Cb[(size_t)m*N + n0 + tn*4 + j] = acc[i][j];
    }
}

// ------------------- GRU recurrence step (both dirs per launch) ------------
// grid (HID/4, R/32, 2), block 128 = 4 units x 32 rows
__global__ void k_gru_step(const float* __restrict__ GI, float* __restrict__ HS,
                           const float* __restrict__ whh, const float* __restrict__ bhh,
                           int R, int s)
{
    int d = blockIdx.z;
    int t = d ? (LSEQ-1-s) : s;
    int tprev = d ? t+1 : t-1;
    int u0 = blockIdx.x * 4;
    int r0 = blockIdx.y * 32;
    int lane = threadIdx.x & 31;
    int ul   = threadIdx.x >> 5;
    int u = u0 + ul;

    __shared__ float sh[256*32];     // h_prev [k][rl]
    __shared__ float sw[3][4][256];  // weights for this block's units

    const float* hp = (s == 0) ? HS
        : HS + ((size_t)tprev*2 + d)*HID*R;
    for (int i = threadIdx.x; i < 256*32; i += 128) {
        int k = i >> 5, rl = i & 31;
        sh[i] = (s == 0) ? 0.f : hp[(size_t)k*R + r0 + rl];
    }
    for (int i = threadIdx.x; i < 3072; i += 128) {
        int k = i & 255, uu = (i >> 8) & 3, g = i >> 10;
        sw[g][uu][k] = whh[((size_t)d*768 + g*256 + u0 + uu)*256 + k];
    }
    __syncthreads();

    const float* w0 = &sw[0][ul][0];
    const float* w1 = &sw[1][ul][0];
    const float* w2 = &sw[2][ul][0];
    float ar = 0.f, az = 0.f, an = 0.f;
#pragma unroll 8
    for (int k = 0; k < 256; k++) {
        float h = sh[k*32 + lane];
        ar = fmaf(w0[k], h, ar);
        az = fmaf(w1[k], h, az);
        an = fmaf(w2[k], h, an);
    }
    const float* gi = GI + ((size_t)t*1536 + d*768)*R;
    float gir = gi[(size_t)(0*256+u)*R + r0 + lane];
    float giz = gi[(size_t)(1*256+u)*R + r0 + lane];
    float gin = gi[(size_t)(2*256+u)*R + r0 + lane];
    float br = bhh[d*768 + u], bz = bhh[d*768 + 256 + u], bn = bhh[d*768 + 512 + u];
    float rg = 1.f / (1.f + expf(-(gir + ar + br)));
    float zg = 1.f / (1.f + expf(-(giz + az + bz)));
    float ng = tanhf(gin + rg * (an + bn));
    float hprev = sh[u*32 + lane];           // zeros at s==0 (filled above)
    float hn = (1.f - zg) * ng + zg * hprev;
    HS[(((size_t)t*2 + d)*HID + u)*R + r0 + lane] = hn;
}

// ------------------- transpose HS[t][d][u][r] -> OUT[r][t][d*256+u] --------
__global__ void k_trans(const float* __restrict__ HS, float* __restrict__ OUT, int R)
{
    int t = blockIdx.x, dd0 = blockIdx.y*32, r0 = blockIdx.z*32;
    __shared__ float tile[32][33];
    int tx = threadIdx.x, ty = threadIdx.y;
#pragma unroll
    for (int i = 0; i < 4; i++) {
        int uu = ty + 8*i;
        int dd = dd0 + uu; int d = dd >> 8, u = dd & 255;
        tile[uu][tx] = HS[(((size_t)t*2 + d)*256 + u)*R + r0 + tx];
    }
    __syncthreads();
#pragma unroll
    for (int i = 0; i < 4; i++) {
        int rr = ty + 8*i;
        OUT[((size_t)(r0+rr)*LSEQ + t)*LD + dd0 + tx] = tile[tx][rr];
    }
}

// ------------------- BiDAF pre: cw, qw, c*w2 -------------------------------
__global__ void k_bidaf_pre(const float* __restrict__ Cseq, const float* __restrict__ Qseq,
                            const float* __restrict__ bw,
                            float* __restrict__ CW, float* __restrict__ QW,
                            float* __restrict__ CW2, int cdiv)
{
    int r = blockIdx.y;
    int i = blockIdx.x*8 + (threadIdx.x >> 5);
    int lane = threadIdx.x & 31;
    const float* c = Cseq + ((size_t)(r >> cdiv)*LSEQ + i)*LD;
    const float* q = Qseq + ((size_t)r*LSEQ + i)*LD;
    float sc = 0.f, sq = 0.f;
    for (int d = lane; d < LD; d += 32) {
        float cv = c[d];
        sc = fmaf(cv, bw[d], sc);
        sq = fmaf(q[d], bw[512 + d], sq);
        CW2[((size_t)r*LSEQ + i)*LD + d] = cv * bw[1024 + d];
    }
#pragma unroll
    for (int o = 16; o; o >>= 1) {
        sc += __shfl_xor_sync(0xffffffffu, sc, o);
        sq += __shfl_xor_sync(0xffffffffu, sq, o);
    }
    if (!lane) { CW[r*LSEQ + i] = sc; QW[r*LSEQ + i] = sq; }
}

// ------------------- softmax over j, capture row max ------------------------
__global__ void k_softmax(float* __restrict__ S, const float* __restrict__ CW,
                          const float* __restrict__ QW, const float* __restrict__ bb,
                          float* __restrict__ Mx)
{
    int r = blockIdx.y, i = blockIdx.x, j = threadIdx.x;
    float bsum = bb[0] + bb[1] + bb[2];
    float* row = S + ((size_t)r*LSEQ + i)*LSEQ;
    float v = row[j] + CW[r*LSEQ + i] + QW[r*LSEQ + j] + bsum;
    __shared__ float red[16];
    float m = v;
#pragma unroll
    for (int o = 16; o; o >>= 1) m = fmaxf(m, __shfl_xor_sync(0xffffffffu, m, o));
    if (!(j & 31)) red[j >> 5] = m;
    __syncthreads();
    float mm = red[0];
#pragma unroll
    for (int w = 1; w < 8; w++) mm = fmaxf(mm, red[w]);
    float e = expf(v - mm);
    float s = e;
#pragma unroll
    for (int o = 16; o; o >>= 1) s += __shfl_xor_sync(0xffffffffu, s, o);
    __syncthreads();
    if (!(j & 31)) red[8 + (j >> 5)] = s;
    __syncthreads();
    float ss = 0.f;
#pragma unroll
    for (int w = 0; w < 8; w++) ss += red[8 + w];
    row[j] = e / ss;
    if (j == 0) Mx[r*LSEQ + i] = mm;
}

// ------------------- q2c: softmax over i of Mx, weighted sum of c ----------
__global__ void k_q2c(const float* __restrict__ Mx, const float* __restrict__ Cseq,
                      float* __restrict__ Q2C, int cdiv)
{
    int r = blockIdx.x, tid = threadIdx.x;
    __shared__ float red[8];
    __shared__ float bbv[256];
    float m = Mx[r*LSEQ + tid];
    float w = m;
#pragma unroll
    for (int o = 16; o; o >>= 1) w = fmaxf(w, __shfl_xor_sync(0xffffffffu, w, o));
    if (!(tid & 31)) red[tid >> 5] = w;
    __syncthreads();
    float mm = red[0];
#pragma unroll
    for (int i = 1; i < 8; i++) mm = fmaxf(mm, red[i]);
    float e = expf(m - mm);
    bbv[tid] = e;
    float s = e;
#pragma unroll
    for (int o = 16; o; o >>= 1) s += __shfl_xor_sync(0xffffffffu, s, o);
    __syncthreads();
    if (!(tid & 31)) red[tid >> 5] = s;
    __syncthreads();
    float ss = 0.f;
#pragma unroll
    for (int i = 0; i < 8; i++) ss += red[i];
    float inv = 1.f / ss;
    const float* cb = Cseq + (size_t)(r >> cdiv)*LSEQ*LD;
    for (int d = tid; d < LD; d += 256) {
        float acc = 0.f;
        for (int i = 0; i < 256; i++) acc = fmaf(bbv[i], cb[(size_t)i*LD + d], acc);
        Q2C[r*LD + d] = acc * inv;
    }
}

// ------------------- attention output assembly + relu ----------------------
__global__ void k_att(const float* __restrict__ Cseq, const float* __restrict__ C2Q,
                      const float* __restrict__ Q2C, float* __restrict__ ATT, int cdiv)
{
    int i = blockIdx.x, r = blockIdx.y, d = threadIdx.x;
    float cv  = Cseq[((size_t)(r >> cdiv)*LSEQ + i)*LD + d];
    float c2q = C2Q [((size_t)r*LSEQ + i)*LD + d];
    float q2c = Q2C [r*LD + d];
    float* o = ATT + ((size_t)i*NR2 + r)*F8;
    o[d]        = fmaxf(cv, 0.f);
    o[512 + d]  = fmaxf(c2q, 0.f);
    o[1024 + d] = fmaxf(cv * c2q, 0.f);
    o[1536 + d] = fmaxf(cv * q2c, 0.f);
}

// ------------------- final: max over k, dot rank_w --------------------------
__global__ void k_final(const float* __restrict__ A1, const float* __restrict__ A2,
                        const float* __restrict__ rw, const float* __restrict__ rb,
                        float* __restrict__ out)
{
    int bo = blockIdx.x, tid = threadIdx.x;       // 1024 threads
    int r0 = bo*2, r1 = r0 + 1;
    float acc = 0.f;
    for (int i = 0; i < LSEQ; i++) {
        const float* a0 = A1 + ((size_t)i*NR2 + r0)*F8;
        const float* a1 = A1 + ((size_t)i*NR2 + r1)*F8;
        const float* b0 = A2 + ((size_t)i*NR2 + r0)*F8;
        const float* b1 = A2 + ((size_t)i*NR2 + r1)*F8;
        const float* w  = rw + (size_t)i*F8;
        for (int f = tid; f < F8; f += 1024) {
            float s0 = a0[f] + b0[f];
            float s1 = a1[f] + b1[f];
            acc = fmaf(w[f], fmaxf(s0, s1), acc);
        }
    }
    __shared__ float red[32];
#pragma unroll
    for (int o = 16; o; o >>= 1) acc += __shfl_xor_sync(0xffffffffu, acc, o);
    if (!(tid & 31)) red[tid >> 5] = acc;
    __syncthreads();
    if (tid == 0) {
        float s = 0.f;
        for (int i = 0; i < 32; i++) s += red[i];
        out[bo] = s + rb[0];
    }
}

// ------------------- host driver -------------------------------------------
extern "C" void kernel_launch(void* const* d_in, const int* in_sizes, int n_in,
                              void* d_out, int out_size)
{
    const int*   q     = (const int*)d_in[0];
    const int*   a     = (const int*)d_in[1];
    const float* emb   = (const float*)d_in[2];
    const float* g1_wih = (const float*)d_in[3];
    const float* g1_whh = (const float*)d_in[4];
    const float* g1_bih = (const float*)d_in[5];
    const float* g1_bhh = (const float*)d_in[6];
    const float* g2_wih = (const float*)d_in[7];
    const float* g2_whh = (const float*)d_in[8];
    const float* g2_bih = (const float*)d_in[9];
    const float* g2_bhh = (const float*)d_in[10];
    const float* b1_w  = (const float*)d_in[11];
    const float* b1_b  = (const float*)d_in[12];
    const float* b2_w  = (const float*)d_in[13];
    const float* b2_b  = (const float*)d_in[14];
    const float* rank_w = (const float*)d_in[15];
    const float* rank_b = (const float*)d_in[16];
    float* out = (float*)d_out;

    float *X1, *GI1, *HS1, *CQ1, *CW2, *S, *CW, *QW, *Mx, *Q2C, *C2Q, *ATT, *GI2, *HS2, *C2, *AT2;
    cudaGetSymbolAddress((void**)&X1,  g_X1);
    cudaGetSymbolAddress((void**)&GI1, g_GI1);
    cudaGetSymbolAddress((void**)&HS1, g_HS1);
    cudaGetSymbolAddress((void**)&CQ1, g_CQ1);
    cudaGetSymbolAddress((void**)&CW2, g_CW2);
    cudaGetSymbolAddress((void**)&S,   g_S);
    cudaGetSymbolAddress((void**)&CW,  g_CW);
    cudaGetSymbolAddress((void**)&QW,  g_QW);
    cudaGetSymbolAddress((void**)&Mx,  g_M);
    cudaGetSymbolAddress((void**)&Q2C, g_Q2C);
    cudaGetSymbolAddress((void**)&C2Q, g_C2Q);
    cudaGetSymbolAddress((void**)&ATT, g_ATT);
    cudaGetSymbolAddress((void**)&GI2, g_GI2);
    cudaGetSymbolAddress((void**)&HS2, g_HS2);
    cudaGetSymbolAddress((void**)&C2,  g_C2);
    cudaGetSymbolAddress((void**)&AT2, g_AT2);

    // 1) embedding
    k_embed<<<dim3(LSEQ, NR1), 64>>>(q, a, emb);

    // 2) GI1 = Wih1 @ X1[t]^T  (batched over t)
    k_gemm_nt<<<dim3(24, 2, LSEQ), 128>>>(g1_wih, X1, GI1, g1_bih,
                                          1536, NR1, VEC, 0, (long)NR1*VEC, (long)1536*NR1);
    // 3) BiGRU-1 recurrence
    for (int s = 0; s < LSEQ; s++)
        k_gru_step<<<dim3(64, NR1/32, 2), 128>>>(GI1, HS1, g1_whh, g1_bhh, NR1, s);
    // 4) transpose to [seq][t][d]
    k_trans<<<dim3(LSEQ, 16, NR1/32), dim3(32, 8)>>>(HS1, CQ1, NR1);

    // 5) BiDAF-1 (c = question enc, q = article enc)
    const float* Qb1 = CQ1 + (size_t)32*LSEQ*LD;
    k_bidaf_pre<<<dim3(32, NR2), 256>>>(CQ1, Qb1, b1_w, CW, QW, CW2, 1);
    k_gemm_nt<<<dim3(4, 4, NR2), 128>>>(CW2, Qb1, S, nullptr,
                                        256, 256, 512, (long)LSEQ*LD, (long)LSEQ*LD, (long)LSEQ*LSEQ);
    k_softmax<<<dim3(LSEQ, NR2), 256>>>(S, CW, QW, b1_b, Mx);
    k_q2c<<<NR2, 256>>>(Mx, CQ1, Q2C, 1);
    k_gemm_nn<<<dim3(4, 8, NR2), 128>>>(S, Qb1, C2Q,
                                        256, 512, 256, (long)LSEQ*LSEQ, (long)LSEQ*LD, (long)LSEQ*LD);
    k_att<<<dim3(LSEQ, NR2), 512>>>(CQ1, C2Q, Q2C, ATT, 1);

    // 6) GI2 = Wih2 @ ATT[t]^T (batched over t)
    k_gemm_nt<<<dim3(24, 1, LSEQ), 128>>>(g2_wih, ATT, GI2, g2_bih,
                                          1536, NR2, F8, 0, (long)NR2*F8, (long)1536*NR2);
    // 7) BiGRU-2
    for (int s = 0; s < LSEQ; s++)
        k_gru_step<<<dim3(64, NR2/32, 2), 128>>>(GI2, HS2, g2_whh, g2_bhh, NR2, s);
    k_trans<<<dim3(LSEQ, 16, NR2/32), dim3(32, 8)>>>(HS2, C2, NR2);

    // 8) BiDAF-2 (self)
    k_bidaf_pre<<<dim3(32, NR2), 256>>>(C2, C2, b2_w, CW, QW, CW2, 0);
    k_gemm_nt<<<dim3(4, 4, NR2), 128>>>(CW2, C2, S, nullptr,
                                        256, 256, 512, (long)LSEQ*LD, (long)LSEQ*LD, (long)LSEQ*LSEQ);
    k_softmax<<<dim3(LSEQ, NR2), 256>>>(S, CW, QW, b2_b, Mx);
    k_q2c<<<NR2, 256>>>(Mx, C2, Q2C, 0);
    k_gemm_nn<<<dim3(4, 8, NR2), 128>>>(S, C2, C2Q,
                                        256, 512, 256, (long)LSEQ*LSEQ, (long)LSEQ*LD, (long)LSEQ*LD);
    k_att<<<dim3(LSEQ, NR2), 512>>>(C2, C2Q, Q2C, AT2, 0);

    // 9) final: s = att + att2, max over k, dot rank_w + rank_b
    k_final<<<32, 1024>>>(ATT, AT2, rank_w, rank_b, out);
}

// round 4
// speedup vs baseline: 1.2026x; 1.2026x over previous
#include <cuda_runtime.h>
#include <math.h>
#include <stdint.h>

#define LSEQ 256
#define VEC  256
#define HID  256
#define NR1  96      // 32 question seqs + 64 article seqs
#define NR2  64      // Beff rows
#define LD   512     // 2*HID
#define F8   2048

// ------------------- scratch (device globals; no allocs) -------------------
__device__ __align__(256) float g_X1 [LSEQ*NR1*VEC];        // [t][row][v]
__device__ __align__(256) float g_GI1[LSEQ*1536*NR1];       // [t][d*768+g*256+u][row]
__device__ __align__(256) float g_HS1[LSEQ*2*HID*NR1];      // [t][d][u][row]
__device__ __align__(256) float g_CQ1[NR1*LSEQ*LD];         // [seq][t][d]
__device__ __align__(256) float g_CW2[NR2*LSEQ*LD];         // [r][i][d]  (c * w2)
__device__ __align__(256) float g_S  [NR2*LSEQ*LSEQ];       // scores then probs
__device__ __align__(256) float g_CW [NR2*LSEQ];
__device__ __align__(256) float g_QW [NR2*LSEQ];
__device__ __align__(256) float g_M  [NR2*LSEQ];
__device__ __align__(256) float g_Q2C[NR2*LD];
__device__ __align__(256) float g_C2Q[NR2*LSEQ*LD];         // [r][i][d]
__device__ __align__(256) float g_ATT[LSEQ*NR2*F8];         // [i][r][f]
__device__ __align__(256) float g_GI2[LSEQ*1536*NR2];
__device__ __align__(256) float g_HS2[LSEQ*2*HID*NR2];
__device__ __align__(256) float g_C2 [NR2*LSEQ*LD];
__device__ __align__(256) float g_AT2[LSEQ*NR2*F8];
__device__ __align__(256) float g_PART[32*16];

// ------------------- packed fp32x2 helpers (Blackwell FFMA2) ---------------
__device__ __forceinline__ void ffma2u(unsigned long long& acc,
                                       unsigned long long a, unsigned long long b) {
    asm("fma.rn.f32x2 %0, %1, %2, %0;" : "+l"(acc) : "l"(a), "l"(b));
}
__device__ __forceinline__ unsigned long long pack2u(float w) {
    unsigned long long r;
    asm("mov.b64 %0, {%1, %1};" : "=l"(r) : "f"(w));
    return r;
}

// ------------------- embedding gather -------------------
__global__ void k_embed(const int* __restrict__ q, const int* __restrict__ a,
                        const float* __restrict__ emb)
{
    int t = blockIdx.x, r = blockIdx.y;
    int tok = (r < 32) ? q[r*LSEQ + t] : a[(r-32)*LSEQ + t];
    const float4* src = (const float4*)(emb + (size_t)tok*VEC);
    float4* dst = (float4*)(g_X1 + ((size_t)t*NR1 + r)*VEC);
    dst[threadIdx.x] = src[threadIdx.x];
}

// ------------------- GEMM NT: C[m][n] = sum_k A[m][k]*B[n][k] (+bias[m]) ---
// BM=128, BN=64, BK=16, 128 threads, 8x8 micro-tile (f32x2 over n pairs).
// M%128==0, K%16==0; N guarded (even N only).
__global__ void k_gemm_nt(const float* __restrict__ A, const float* __restrict__ B,
                          float* __restrict__ C, const float* __restrict__ bias,
                          int M, int N, int K, long sA, long sB, long sC)
{
    const float* Ab = A + (size_t)blockIdx.z * sA;
    const float* Bb = B + (size_t)blockIdx.z * sB;
    float* Cb = C + (size_t)blockIdx.z * sC;
    int m0 = blockIdx.x * 128, n0 = blockIdx.y * 64;
    int tid = threadIdx.x;
    int tn = tid & 7, tm = tid >> 3;          // tm 0..15, tn 0..7
    __shared__ float As[16][132];
    __shared__ float Bs[16][68];
    unsigned long long acc[8][4];
#pragma unroll
    for (int i = 0; i < 8; i++)
#pragma unroll
        for (int j = 0; j < 4; j++) acc[i][j] = 0ull;

    for (int k0 = 0; k0 < K; k0 += 16) {
#pragma unroll
        for (int it = 0; it < 4; it++) {
            int idx = tid + it*128;
            int row = idx >> 2, c4 = idx & 3;
            float4 v = *(const float4*)(Ab + (size_t)(m0+row)*K + k0 + c4*4);
            As[c4*4+0][row]=v.x; As[c4*4+1][row]=v.y; As[c4*4+2][row]=v.z; As[c4*4+3][row]=v.w;
        }
#pragma unroll
        for (int it = 0; it < 2; it++) {
            int idx = tid + it*128;
            int row = idx >> 2, c4 = idx & 3;
            float4 v = make_float4(0.f,0.f,0.f,0.f);
            if (n0 + row < N) v = *(const float4*)(Bb + (size_t)(n0+row)*K + k0 + c4*4);
            Bs[c4*4+0][row]=v.x; Bs[c4*4+1][row]=v.y; Bs[c4*4+2][row]=v.z; Bs[c4*4+3][row]=v.w;
        }
        __syncthreads();
#pragma unroll
        for (int kk = 0; kk < 16; kk++) {
            float a[8];
            *(float4*)(a)   = *(const float4*)&As[kk][tm*8];
            *(float4*)(a+4) = *(const float4*)&As[kk][tm*8+4];
            ulonglong2 b01 = *(const ulonglong2*)&Bs[kk][tn*8];
            ulonglong2 b23 = *(const ulonglong2*)&Bs[kk][tn*8+4];
#pragma unroll
            for (int i = 0; i < 8; i++) {
                unsigned long long ai = pack2u(a[i]);
                ffma2u(acc[i][0], ai, b01.x);
                ffma2u(acc[i][1], ai, b01.y);
                ffma2u(acc[i][2], ai, b23.x);
                ffma2u(acc[i][3], ai, b23.y);
            }
        }
        __syncthreads();
    }
#pragma unroll
    for (int i = 0; i < 8; i++) {
        int m = m0 + tm*8 + i;
        float bi = bias ? bias[m] : 0.f;
#pragma unroll
        for (int j = 0; j < 4; j++) {
            int n = n0 + tn*8 + j*2;
            if (n < N) {
                float2 v = *(float2*)&acc[i][j];
                v.x += bi; v.y += bi;
                *(float2*)(Cb + (size_t)m*N + n) = v;
            }
        }
    }
}

// ------------------- GEMM NN: C[m][n] = sum_k A[m][k]*B[k][n] --------------
// BM=128, BN=64, BK=16, 128 threads, 8x8 micro. M%128==0, N%64==0, K%16==0.
__global__ void k_gemm_nn(const float* __restrict__ A, const float* __restrict__ B,
                          float* __restrict__ C,
                          int M, int N, int K, long sA, long sB, long sC)
{
    const float* Ab = A + (size_t)blockIdx.z * sA;
    const float* Bb = B + (size_t)blockIdx.z * sB;
    float* Cb = C + (size_t)blockIdx.z * sC;
    int m0 = blockIdx.x * 128, n0 = blockIdx.y * 64;
    int tid = threadIdx.x;
    int tn = tid & 7, tm = tid >> 3;
    __shared__ float As[16][132];
    __shared__ float Bs[16][68];
    unsigned long long acc[8][4];
#pragma unroll
    for (int i = 0; i < 8; i++)
#pragma unroll
        for (int j = 0; j < 4; j++) acc[i][j] = 0ull;

    for (int k0 = 0; k0 < K; k0 += 16) {
#pragma unroll
        for (int it = 0; it < 4; it++) {
            int idx = tid + it*128;
            int row = idx >> 2, c4 = idx & 3;
            float4 v = *(const float4*)(Ab + (size_t)(m0+row)*K + k0 + c4*4);
            As[c4*4+0][row]=v.x; As[c4*4+1][row]=v.y; As[c4*4+2][row]=v.z; As[c4*4+3][row]=v.w;
        }
#pragma unroll
        for (int it = 0; it < 2; it++) {
            int idx = tid + it*128;
            int row = idx >> 4, c4 = idx & 15;
            float4 v = *(const float4*)(Bb + (size_t)(k0+row)*N + n0 + c4*4);
            *(float4*)&Bs[row][c4*4] = v;
        }
        __syncthreads();
#pragma unroll
        for (int kk = 0; kk < 16; kk++) {
            float a[8];
            *(float4*)(a)   = *(const float4*)&As[kk][tm*8];
            *(float4*)(a+4) = *(const float4*)&As[kk][tm*8+4];
            ulonglong2 b01 = *(const ulonglong2*)&Bs[kk][tn*8];
            ulonglong2 b23 = *(const ulonglong2*)&Bs[kk][tn*8+4];
#pragma unroll
            for (int i = 0; i < 8; i++) {
                unsigned long long ai = pack2u(a[i]);
                ffma2u(acc[i][0], ai, b01.x);
                ffma2u(acc[i][1], ai, b01.y);
                ffma2u(acc[i][2], ai, b23.x);
                ffma2u(acc[i][3], ai, b23.y);
            }
        }
        __syncthreads();
    }
#pragma unroll
    for (int i = 0; i < 8; i++) {
        int m = m0 + tm*8 + i;
#pragma unroll
        for (int j = 0; j < 4; j++) {
            float2 v = *(float2*)&acc[i][j];
            *(float2*)(Cb + (size_t)m*N + n0 + tn*8 + j*2) = v;
        }
    }
}

// ------------------- GRU recurrence step v2 ---------------------------------
// grid (16, R/32, 2), block 128 = 16 units x 8 row-quads (4 rows/thread)
// dyn smem: sh[256][16] float2 (32KB) + sw[3][16][256] float2-dup (96KB)
__global__ void k_gru_step(const float* __restrict__ GI, float* __restrict__ HS,
                           const float* __restrict__ whh, const float* __restrict__ bhh,
                           int R, int s)
{
    extern __shared__ char smem[];
    float2* sh = (float2*)smem;                       // [k*16 + rp]
    float2* sw = (float2*)(smem + 256*16*8);          // [(g*16+ul)*256 + k]

    int d = blockIdx.z;
    int t = d ? (LSEQ-1-s) : s;
    int tprev = d ? t+1 : t-1;
    int u0 = blockIdx.x * 16;
    int r0 = blockIdx.y * 32;
    int tid = threadIdx.x;
    int rq = tid & 7;
    int ul = tid >> 3;
    int u = u0 + ul;

    // stage h_prev [256 units][16 row-pairs]
    if (s == 0) {
        for (int i = tid; i < 256*16; i += 128) sh[i] = make_float2(0.f, 0.f);
    } else {
        const float* hp = HS + ((size_t)tprev*2 + d)*HID*R;
        for (int i = tid; i < 256*16; i += 128) {
            int k = i >> 4, rp = i & 15;
            sh[i] = *(const float2*)&hp[(size_t)k*R + r0 + rp*2];
        }
    }
    // stage weights, duplicated into f32x2 lanes
#pragma unroll
    for (int g = 0; g < 3; g++) {
        const float4* src = (const float4*)(whh + ((size_t)(d*768 + g*256 + u0))*256);
        float2* dst = sw + (size_t)g*16*256;
        for (int i = tid; i < 1024; i += 128) {
            float4 v = src[i];
            dst[i*4+0] = make_float2(v.x, v.x);
            dst[i*4+1] = make_float2(v.y, v.y);
            dst[i*4+2] = make_float2(v.z, v.z);
            dst[i*4+3] = make_float2(v.w, v.w);
        }
    }
    __syncthreads();

    const float2* w0 = sw + (0*16 + ul)*256;
    const float2* w1 = sw + (1*16 + ul)*256;
    const float2* w2 = sw + (2*16 + ul)*256;
    int rp0 = rq*2;

    unsigned long long ar0=0, ar1=0, az0=0, az1=0, an0=0, an1=0;
#pragma unroll 8
    for (int k = 0; k < 256; k++) {
        unsigned long long h0 = *(const unsigned long long*)&sh[k*16 + rp0];
        unsigned long long h1 = *(const unsigned long long*)&sh[k*16 + rp0 + 1];
        unsigned long long W;
        W = *(const unsigned long long*)&w0[k]; ffma2u(ar0, W, h0); ffma2u(ar1, W, h1);
        W = *(const unsigned long long*)&w1[k]; ffma2u(az0, W, h0); ffma2u(az1, W, h1);
        W = *(const unsigned long long*)&w2[k]; ffma2u(an0, W, h0); ffma2u(an1, W, h1);
    }

    const float* gi = GI + ((size_t)t*1536 + (size_t)d*768)*R;
    int rbase = r0 + rq*4;
    float4 gr = *(const float4*)&gi[(size_t)(0*256+u)*R + rbase];
    float4 gz = *(const float4*)&gi[(size_t)(1*256+u)*R + rbase];
    float4 gn = *(const float4*)&gi[(size_t)(2*256+u)*R + rbase];
    float br = bhh[d*768 + u], bz = bhh[d*768 + 256 + u], bn = bhh[d*768 + 512 + u];

    float2 hA = sh[u*16 + rp0], hB = sh[u*16 + rp0 + 1];
    float hprev[4] = {hA.x, hA.y, hB.x, hB.y};
    float arr[4] = {((float2*)&ar0)->x, ((float2*)&ar0)->y, ((float2*)&ar1)->x, ((float2*)&ar1)->y};
    float azz[4] = {((float2*)&az0)->x, ((float2*)&az0)->y, ((float2*)&az1)->x, ((float2*)&az1)->y};
    float ann[4] = {((float2*)&an0)->x, ((float2*)&an0)->y, ((float2*)&an1)->x, ((float2*)&an1)->y};
    float gri[4] = {gr.x, gr.y, gr.z, gr.w};
    float gzi[4] = {gz.x, gz.y, gz.z, gz.w};
    float gni[4] = {gn.x, gn.y, gn.z, gn.w};
    float out[4];
#pragma unroll
    for (int j = 0; j < 4; j++) {
        float rg = 1.f / (1.f + expf(-(gri[j] + arr[j] + br)));
        float zg = 1.f / (1.f + expf(-(gzi[j] + azz[j] + bz)));
        float ng = tanhf(gni[j] + rg * (ann[j] + bn));
        out[j] = (1.f - zg) * ng + zg * hprev[j];
    }
    *(float4*)&HS[(((size_t)t*2 + d)*HID + u)*R + rbase] = *(float4*)out;
}

// ------------------- transpose HS[t][d][u][r] -> OUT[r][t][d*256+u] --------
__global__ void k_trans(const float* __restrict__ HS, float* __restrict__ OUT, int R)
{
    int t = blockIdx.x, dd0 = blockIdx.y*32, r0 = blockIdx.z*32;
    __shared__ float tile[32][33];
    int tx = threadIdx.x, ty = threadIdx.y;
#pragma unroll
    for (int i = 0; i < 4; i++) {
        int uu = ty + 8*i;
        int dd = dd0 + uu; int d = dd >> 8, u = dd & 255;
        tile[uu][tx] = HS[(((size_t)t*2 + d)*256 + u)*R + r0 + tx];
    }
    __syncthreads();
#pragma unroll
    for (int i = 0; i < 4; i++) {
        int rr = ty + 8*i;
        OUT[((size_t)(r0+rr)*LSEQ + t)*LD + dd0 + tx] = tile[tx][rr];
    }
}

// ------------------- BiDAF pre: cw, qw, c*w2 -------------------------------
__global__ void k_bidaf_pre(const float* __restrict__ Cseq, const float* __restrict__ Qseq,
                            const float* __restrict__ bw,
                            float* __restrict__ CW, float* __restrict__ QW,
                            float* __restrict__ CW2, int cdiv)
{
    int r = blockIdx.y;
    int i = blockIdx.x*8 + (threadIdx.x >> 5);
    int lane = threadIdx.x & 31;
    const float* c = Cseq + ((size_t)(r >> cdiv)*LSEQ + i)*LD;
    const float* q = Qseq + ((size_t)r*LSEQ + i)*LD;
    float sc = 0.f, sq = 0.f;
    for (int d = lane; d < LD; d += 32) {
        float cv = c[d];
        sc = fmaf(cv, bw[d], sc);
        sq = fmaf(q[d], bw[512 + d], sq);
        CW2[((size_t)r*LSEQ + i)*LD + d] = cv * bw[1024 + d];
    }
#pragma unroll
    for (int o = 16; o; o >>= 1) {
        sc += __shfl_xor_sync(0xffffffffu, sc, o);
        sq += __shfl_xor_sync(0xffffffffu, sq, o);
    }
    if (!lane) { CW[r*LSEQ + i] = sc; QW[r*LSEQ + i] = sq; }
}

// ------------------- softmax over j, capture row max ------------------------
__global__ void k_softmax(float* __restrict__ S, const float* __restrict__ CW,
                          const float* __restrict__ QW, const float* __restrict__ bb,
                          float* __restrict__ Mx)
{
    int r = blockIdx.y, i = blockIdx.x, j = threadIdx.x;
    float bsum = bb[0] + bb[1] + bb[2];
    float* row = S + ((size_t)r*LSEQ + i)*LSEQ;
    float v = row[j] + CW[r*LSEQ + i] + QW[r*LSEQ + j] + bsum;
    __shared__ float red[16];
    float m = v;
#pragma unroll
    for (int o = 16; o; o >>= 1) m = fmaxf(m, __shfl_xor_sync(0xffffffffu, m, o));
    if (!(j & 31)) red[j >> 5] = m;
    __syncthreads();
    float mm = red[0];
#pragma unroll
    for (int w = 1; w < 8; w++) mm = fmaxf(mm, red[w]);
    float e = expf(v - mm);
    float s = e;
#pragma unroll
    for (int o = 16; o; o >>= 1) s += __shfl_xor_sync(0xffffffffu, s, o);
    __syncthreads();
    if (!(j & 31)) red[8 + (j >> 5)] = s;
    __syncthreads();
    float ss = 0.f;
#pragma unroll
    for (int w = 0; w < 8; w++) ss += red[8 + w];
    row[j] = e / ss;
    if (j == 0) Mx[r*LSEQ + i] = mm;
}

// ------------------- q2c ----------------------------------------------------
__global__ void k_q2c(const float* __restrict__ Mx, const float* __restrict__ Cseq,
                      float* __restrict__ Q2C, int cdiv)
{
    int r = blockIdx.x, tid = threadIdx.x;
    __shared__ float red[8];
    __shared__ float bbv[256];
    float m = Mx[r*LSEQ + tid];
    float w = m;
#pragma unroll
    for (int o = 16; o; o >>= 1) w = fmaxf(w, __shfl_xor_sync(0xffffffffu, w, o));
    if (!(tid & 31)) red[tid >> 5] = w;
    __syncthreads();
    float mm = red[0];
#pragma unroll
    for (int i = 1; i < 8; i++) mm = fmaxf(mm, red[i]);
    float e = expf(m - mm);
    bbv[tid] = e;
    float s = e;
#pragma unroll
    for (int o = 16; o; o >>= 1) s += __shfl_xor_sync(0xffffffffu, s, o);
    __syncthreads();
    if (!(tid & 31)) red[tid >> 5] = s;
    __syncthreads();
    float ss = 0.f;
#pragma unroll
    for (int i = 0; i < 8; i++) ss += red[i];
    float inv = 1.f / ss;
    const float* cb = Cseq + (size_t)(r >> cdiv)*LSEQ*LD;
    for (int d = tid; d < LD; d += 256) {
        float acc = 0.f;
        for (int i = 0; i < 256; i++) acc = fmaf(bbv[i], cb[(size_t)i*LD + d], acc);
        Q2C[r*LD + d] = acc * inv;
    }
}

// ------------------- attention output assembly + relu ----------------------
__global__ void k_att(const float* __restrict__ Cseq, const float* __restrict__ C2Q,
                      const float* __restrict__ Q2C, float* __restrict__ ATT, int cdiv)
{
    int i = blockIdx.x, r = blockIdx.y, d = threadIdx.x;
    float cv  = Cseq[((size_t)(r >> cdiv)*LSEQ + i)*LD + d];
    float c2q = C2Q [((size_t)r*LSEQ + i)*LD + d];
    float q2c = Q2C [r*LD + d];
    float* o = ATT + ((size_t)i*NR2 + r)*F8;
    o[d]        = fmaxf(cv, 0.f);
    o[512 + d]  = fmaxf(c2q, 0.f);
    o[1024 + d] = fmaxf(cv * c2q, 0.f);
    o[1536 + d] = fmaxf(cv * q2c, 0.f);
}

// ------------------- final: max over k, dot rank_w (2-phase) ----------------
__global__ void k_final1(const float* __restrict__ A1, const float* __restrict__ A2,
                         const float* __restrict__ rw, float* __restrict__ part)
{
    int bo = blockIdx.x, tile = blockIdx.y, tid = threadIdx.x;  // 256 threads
    int r0 = bo*2, r1 = r0 + 1;
    float acc = 0.f;
    for (int ii = 0; ii < 16; ii++) {
        int i = tile*16 + ii;
        size_t base0 = ((size_t)i*NR2 + r0)*F8;
        size_t base1 = ((size_t)i*NR2 + r1)*F8;
        const float4* a0 = (const float4*)(A1 + base0);
        const float4* a1 = (const float4*)(A1 + base1);
        const float4* b0 = (const float4*)(A2 + base0);
        const float4* b1 = (const float4*)(A2 + base1);
        const float4* w  = (const float4*)(rw + (size_t)i*F8);
#pragma unroll
        for (int f = tid; f < 512; f += 256) {
            float4 x0 = a0[f], x1 = a1[f], y0 = b0[f], y1 = b1[f], wv = w[f];
            acc = fmaf(wv.x, fmaxf(x0.x + y0.x, x1.x + y1.x), acc);
            acc = fmaf(wv.y, fmaxf(x0.y + y0.y, x1.y + y1.y), acc);
            acc = fmaf(wv.z, fmaxf(x0.z + y0.z, x1.z + y1.z), acc);
            acc = fmaf(wv.w, fmaxf(x0.w + y0.w, x1.w + y1.w), acc);
        }
    }
    __shared__ float red[8];
#pragma unroll
    for (int o = 16; o; o >>= 1) acc += __shfl_xor_sync(0xffffffffu, acc, o);
    if (!(tid & 31)) red[tid >> 5] = acc;
    __syncthreads();
    if (tid == 0) {
        float s = 0.f;
        for (int i = 0; i < 8; i++) s += red[i];
        part[bo*16 + tile] = s;
    }
}

__global__ void k_final2(const float* __restrict__ part, const float* __restrict__ rb,
                         float* __restrict__ out)
{
    int bo = threadIdx.x;   // 32
    float s = 0.f;
    for (int t = 0; t < 16; t++) s += part[bo*16 + t];
    out[bo] = s + rb[0];
}

// ------------------- host driver -------------------------------------------
extern "C" void kernel_launch(void* const* d_in, const int* in_sizes, int n_in,
                              void* d_out, int out_size)
{
    const int*   q     = (const int*)d_in[0];
    const int*   a     = (const int*)d_in[1];
    const float* emb   = (const float*)d_in[2];
    const float* g1_wih = (const float*)d_in[3];
    const float* g1_whh = (const float*)d_in[4];
    const float* g1_bih = (const float*)d_in[5];
    const float* g1_bhh = (const float*)d_in[6];
    const float* g2_wih = (const float*)d_in[7];
    const float* g2_whh = (const float*)d_in[8];
    const float* g2_bih = (const float*)d_in[9];
    const float* g2_bhh = (const float*)d_in[10];
    const float* b1_w  = (const float*)d_in[11];
    const float* b1_b  = (const float*)d_in[12];
    const float* b2_w  = (const float*)d_in[13];
    const float* b2_b  = (const float*)d_in[14];
    const float* rank_w = (const float*)d_in[15];
    const float* rank_b = (const float*)d_in[16];
    float* out = (float*)d_out;

    float *X1, *GI1, *HS1, *CQ1, *CW2, *S, *CW, *QW, *Mx, *Q2C, *C2Q, *ATT, *GI2, *HS2, *C2, *AT2, *PART;
    cudaGetSymbolAddress((void**)&X1,  g_X1);
    cudaGetSymbolAddress((void**)&GI1, g_GI1);
    cudaGetSymbolAddress((void**)&HS1, g_HS1);
    cudaGetSymbolAddress((void**)&CQ1, g_CQ1);
    cudaGetSymbolAddress((void**)&CW2, g_CW2);
    cudaGetSymbolAddress((void**)&S,   g_S);
    cudaGetSymbolAddress((void**)&CW,  g_CW);
    cudaGetSymbolAddress((void**)&QW,  g_QW);
    cudaGetSymbolAddress((void**)&Mx,  g_M);
    cudaGetSymbolAddress((void**)&Q2C, g_Q2C);
    cudaGetSymbolAddress((void**)&C2Q, g_C2Q);
    cudaGetSymbolAddress((void**)&ATT, g_ATT);
    cudaGetSymbolAddress((void**)&GI2, g_GI2);
    cudaGetSymbolAddress((void**)&HS2, g_HS2);
    cudaGetSymbolAddress((void**)&C2,  g_C2);
    cudaGetSymbolAddress((void**)&AT2, g_AT2);
    cudaGetSymbolAddress((void**)&PART, g_PART);

    const int GRU_SMEM = 256*16*8 + 3*16*256*8;   // 32KB + 96KB = 128KB
    cudaFuncSetAttribute(k_gru_step, cudaFuncAttributeMaxDynamicSharedMemorySize, GRU_SMEM);

    // 1) embedding
    k_embed<<<dim3(LSEQ, NR1), 64>>>(q, a, emb);

    // 2) GI1 = Wih1 @ X1[t]^T  (batched over t)
    k_gemm_nt<<<dim3(12, 2, LSEQ), 128>>>(g1_wih, X1, GI1, g1_bih,
                                          1536, NR1, VEC, 0, (long)NR1*VEC, (long)1536*NR1);
    // 3) BiGRU-1 recurrence
    for (int s = 0; s < LSEQ; s++)
        k_gru_step<<<dim3(16, NR1/32, 2), 128, GRU_SMEM>>>(GI1, HS1, g1_whh, g1_bhh, NR1, s);
    // 4) transpose to [seq][t][d]
    k_trans<<<dim3(LSEQ, 16, NR1/32), dim3(32, 8)>>>(HS1, CQ1, NR1);

    // 5) BiDAF-1 (c = question enc, q = article enc)
    const float* Qb1 = CQ1 + (size_t)32*LSEQ*LD;
    k_bidaf_pre<<<dim3(32, NR2), 256>>>(CQ1, Qb1, b1_w, CW, QW, CW2, 1);
    k_gemm_nt<<<dim3(2, 4, NR2), 128>>>(CW2, Qb1, S, nullptr,
                                        256, 256, 512, (long)LSEQ*LD, (long)LSEQ*LD, (long)LSEQ*LSEQ);
    k_softmax<<<dim3(LSEQ, NR2), 256>>>(S, CW, QW, b1_b, Mx);
    k_q2c<<<NR2, 256>>>(Mx, CQ1, Q2C, 1);
    k_gemm_nn<<<dim3(2, 8, NR2), 128>>>(S, Qb1, C2Q,
                                        256, 512, 256, (long)LSEQ*LSEQ, (long)LSEQ*LD, (long)LSEQ*LD);
    k_att<<<dim3(LSEQ, NR2), 512>>>(CQ1, C2Q, Q2C, ATT, 1);

    // 6) GI2 = Wih2 @ ATT[t]^T (batched over t)
    k_gemm_nt<<<dim3(12, 1, LSEQ), 128>>>(g2_wih, ATT, GI2, g2_bih,
                                          1536, NR2, F8, 0, (long)NR2*F8, (long)1536*NR2);
    // 7) BiGRU-2
    for (int s = 0; s < LSEQ; s++)
        k_gru_step<<<dim3(16, NR2/32, 2), 128, GRU_SMEM>>>(GI2, HS2, g2_whh, g2_bhh, NR2, s);
    k_trans<<<dim3(LSEQ, 16, NR2/32), dim3(32, 8)>>>(HS2, C2, NR2);

    // 8) BiDAF-2 (self)
    k_bidaf_pre<<<dim3(32, NR2), 256>>>(C2, C2, b2_w, CW, QW, CW2, 0);
    k_gemm_nt<<<dim3(2, 4, NR2), 128>>>(CW2, C2, S, nullptr,
                                        256, 256, 512, (long)LSEQ*LD, (long)LSEQ*LD, (long)LSEQ*LSEQ);
    k_softmax<<<dim3(LSEQ, NR2), 256>>>(S, CW, QW, b2_b, Mx);
    k_q2c<<<NR2, 256>>>(Mx, C2, Q2C, 0);
    k_gemm_nn<<<dim3(2, 8, NR2), 128>>>(S, C2, C2Q,
                                        256, 512, 256, (long)LSEQ*LSEQ, (long)LSEQ*LD, (long)LSEQ*LD);
    k_att<<<dim3(LSEQ, NR2), 512>>>(C2, C2Q, Q2C, AT2, 0);

    // 9) final
    k_final1<<<dim3(32, 16), 256>>>(ATT, AT2, rank_w, PART);
    k_final2<<<1, 32>>>(PART, rank_b, out);
}

// round 6
// speedup vs baseline: 1.7810x; 1.4809x over previous
#include <cuda_runtime.h>
#include <math.h>
#include <stdint.h>

#define LSEQ 256
#define VEC  256
#define HID  256
#define NR1  96      // 32 question seqs + 64 article seqs
#define NR2  64      // Beff rows
#define LD   512     // 2*HID
#define F8   2048

#define RPS   16     // rows per slab (per cluster)
#define UPC   32     // units per CTA
#define CSZ   8      // cluster size
#define HPAD  258    // padded row stride (floats) in h buffer

// ------------------- scratch (device globals; no allocs) -------------------
__device__ __align__(256) float g_X1 [LSEQ*NR1*VEC];
__device__ __align__(256) float g_GI1[LSEQ*1536*NR1];
__device__ __align__(256) float g_HS1[LSEQ*2*HID*NR1];
__device__ __align__(256) float g_CQ1[NR1*LSEQ*LD];
__device__ __align__(256) float g_CW2[NR2*LSEQ*LD];
__device__ __align__(256) float g_S  [NR2*LSEQ*LSEQ];
__device__ __align__(256) float g_CW [NR2*LSEQ];
__device__ __align__(256) float g_QW [NR2*LSEQ];
__device__ __align__(256) float g_M  [NR2*LSEQ];
__device__ __align__(256) float g_Q2C[NR2*LD];
__device__ __align__(256) float g_C2Q[NR2*LSEQ*LD];
__device__ __align__(256) float g_ATT[LSEQ*NR2*F8];
__device__ __align__(256) float g_GI2[LSEQ*1536*NR2];
__device__ __align__(256) float g_HS2[LSEQ*2*HID*NR2];
__device__ __align__(256) float g_C2 [NR2*LSEQ*LD];
__device__ __align__(256) float g_AT2[LSEQ*NR2*F8];
__device__ __align__(256) float g_PART[32*16];

// ------------------- packed fp32x2 helpers ---------------------------------
__device__ __forceinline__ void ffma2u(unsigned long long& acc,
                                       unsigned long long a, unsigned long long b) {
    asm("fma.rn.f32x2 %0, %1, %2, %0;" : "+l"(acc) : "l"(a), "l"(b));
}
__device__ __forceinline__ unsigned long long pack2u(float w) {
    unsigned long long r;
    asm("mov.b64 %0, {%1, %1};" : "=l"(r) : "f"(w));
    return r;
}

// ------------------- cluster helpers ----------------------------------------
__device__ __forceinline__ uint32_t smem_u32(const void* p) {
    return (uint32_t)__cvta_generic_to_shared(p);
}
__device__ __forceinline__ uint32_t mapa_u32(uint32_t addr, uint32_t rank) {
    uint32_t r;
    asm("mapa.shared::cluster.u32 %0, %1, %2;" : "=r"(r) : "r"(addr), "r"(rank));
    return r;
}
__device__ __forceinline__ void st_cluster64(uint32_t addr, float2 v) {
    asm volatile("st.shared::cluster.b64 [%0], %1;"
                 :: "r"(addr), "l"(*(unsigned long long*)&v) : "memory");
}
__device__ __forceinline__ void cluster_sync_() {
    asm volatile("barrier.cluster.arrive.aligned;" ::: "memory");
    asm volatile("barrier.cluster.wait.aligned;" ::: "memory");
}

// ------------------- embedding gather ---------------------------------------
__global__ void k_embed(const int* __restrict__ q, const int* __restrict__ a,
                        const float* __restrict__ emb)
{
    int t = blockIdx.x, r = blockIdx.y;
    int tok = (r < 32) ? q[r*LSEQ + t] : a[(r-32)*LSEQ + t];
    const float4* src = (const float4*)(emb + (size_t)tok*VEC);
    float4* dst = (float4*)(g_X1 + ((size_t)t*NR1 + r)*VEC);
    dst[threadIdx.x] = src[threadIdx.x];
}

// ------------------- GEMM NT (BM=128,BN=64,BK=16, f32x2) --------------------
__global__ void k_gemm_nt(const float* __restrict__ A, const float* __restrict__ B,
                          float* __restrict__ C, const float* __restrict__ bias,
                          int M, int N, int K, long sA, long sB, long sC)
{
    const float* Ab = A + (size_t)blockIdx.z * sA;
    const float* Bb = B + (size_t)blockIdx.z * sB;
    float* Cb = C + (size_t)blockIdx.z * sC;
    int m0 = blockIdx.x * 128, n0 = blockIdx.y * 64;
    int tid = threadIdx.x;
    int tn = tid & 7, tm = tid >> 3;
    __shared__ float As[16][132];
    __shared__ float Bs[16][68];
    unsigned long long acc[8][4];
#pragma unroll
    for (int i = 0; i < 8; i++)
#pragma unroll
        for (int j = 0; j < 4; j++) acc[i][j] = 0ull;

    for (int k0 = 0; k0 < K; k0 += 16) {
#pragma unroll
        for (int it = 0; it < 4; it++) {
            int idx = tid + it*128;
            int row = idx >> 2, c4 = idx & 3;
            float4 v = *(const float4*)(Ab + (size_t)(m0+row)*K + k0 + c4*4);
            As[c4*4+0][row]=v.x; As[c4*4+1][row]=v.y; As[c4*4+2][row]=v.z; As[c4*4+3][row]=v.w;
        }
#pragma unroll
        for (int it = 0; it < 2; it++) {
            int idx = tid + it*128;
            int row = idx >> 2, c4 = idx & 3;
            float4 v = make_float4(0.f,0.f,0.f,0.f);
            if (n0 + row < N) v = *(const float4*)(Bb + (size_t)(n0+row)*K + k0 + c4*4);
            Bs[c4*4+0][row]=v.x; Bs[c4*4+1][row]=v.y; Bs[c4*4+2][row]=v.z; Bs[c4*4+3][row]=v.w;
        }
        __syncthreads();
#pragma unroll
        for (int kk = 0; kk < 16; kk++) {
            float a[8];
            *(float4*)(a)   = *(const float4*)&As[kk][tm*8];
            *(float4*)(a+4) = *(const float4*)&As[kk][tm*8+4];
            ulonglong2 b01 = *(const ulonglong2*)&Bs[kk][tn*8];
            ulonglong2 b23 = *(const ulonglong2*)&Bs[kk][tn*8+4];
#pragma unroll
            for (int i = 0; i < 8; i++) {
                unsigned long long ai = pack2u(a[i]);
                ffma2u(acc[i][0], ai, b01.x);
                ffma2u(acc[i][1], ai, b01.y);
                ffma2u(acc[i][2], ai, b23.x);
                ffma2u(acc[i][3], ai, b23.y);
            }
        }
        __syncthreads();
    }
#pragma unroll
    for (int i = 0; i < 8; i++) {
        int m = m0 + tm*8 + i;
        float bi = bias ? bias[m] : 0.f;
#pragma unroll
        for (int j = 0; j < 4; j++) {
            int n = n0 + tn*8 + j*2;
            if (n < N) {
                float2 v = *(float2*)&acc[i][j];
                v.x += bi; v.y += bi;
                *(float2*)(Cb + (size_t)m*N + n) = v;
            }
        }
    }
}

// ------------------- GEMM NN (BM=128,BN=64,BK=16, f32x2) --------------------
__global__ void k_gemm_nn(const float* __restrict__ A, const float* __restrict__ B,
                          float* __restrict__ C,
                          int M, int N, int K, long sA, long sB, long sC)
{
    const float* Ab = A + (size_t)blockIdx.z * sA;
    const float* Bb = B + (size_t)blockIdx.z * sB;
    float* Cb = C + (size_t)blockIdx.z * sC;
    int m0 = blockIdx.x * 128, n0 = blockIdx.y * 64;
    int tid = threadIdx.x;
    int tn = tid & 7, tm = tid >> 3;
    __shared__ float As[16][132];
    __shared__ float Bs[16][68];
    unsigned long long acc[8][4];
#pragma unroll
    for (int i = 0; i < 8; i++)
#pragma unroll
        for (int j = 0; j < 4; j++) acc[i][j] = 0ull;

    for (int k0 = 0; k0 < K; k0 += 16) {
#pragma unroll
        for (int it = 0; it < 4; it++) {
            int idx = tid + it*128;
            int row = idx >> 2, c4 = idx & 3;
            float4 v = *(const float4*)(Ab + (size_t)(m0+row)*K + k0 + c4*4);
            As[c4*4+0][row]=v.x; As[c4*4+1][row]=v.y; As[c4*4+2][row]=v.z; As[c4*4+3][row]=v.w;
        }
#pragma unroll
        for (int it = 0; it < 2; it++) {
            int idx = tid + it*128;
            int row = idx >> 4, c4 = idx & 15;
            float4 v = *(const float4*)(Bb + (size_t)(k0+row)*N + n0 + c4*4);
            *(float4*)&Bs[row][c4*4] = v;
        }
        __syncthreads();
#pragma unroll
        for (int kk = 0; kk < 16; kk++) {
            float a[8];
            *(float4*)(a)   = *(const float4*)&As[kk][tm*8];
            *(float4*)(a+4) = *(const float4*)&As[kk][tm*8+4];
            ulonglong2 b01 = *(const ulonglong2*)&Bs[kk][tn*8];
            ulonglong2 b23 = *(const ulonglong2*)&Bs[kk][tn*8+4];
#pragma unroll
            for (int i = 0; i < 8; i++) {
                unsigned long long ai = pack2u(a[i]);
                ffma2u(acc[i][0], ai, b01.x);
                ffma2u(acc[i][1], ai, b01.y);
                ffma2u(acc[i][2], ai, b23.x);
                ffma2u(acc[i][3], ai, b23.y);
            }
        }
        __syncthreads();
    }
#pragma unroll
    for (int i = 0; i < 8; i++) {
        int m = m0 + tm*8 + i;
#pragma unroll
        for (int j = 0; j < 4; j++) {
            float2 v = *(float2*)&acc[i][j];
            *(float2*)(Cb + (size_t)m*N + n0 + tn*8 + j*2) = v;
        }
    }
}

// ------------------- persistent cluster GRU ---------------------------------
// grid = (#slabs * 2 dirs) clusters of 8 CTAs; block = 256 threads.
// CTA owns (dir, 16-row slab, 32 units). W_hh slice staged to smem ONCE.
// h double-buffered in smem (all 256 units x 16 rows); after each step every
// CTA pushes its 32-unit h_new slice into all 8 CTAs' next buffer via DSMEM.
// thread: row = tid&15, up = tid>>4 (unit pair u0+2*up, u0+2*up+1)
__global__ void __cluster_dims__(CSZ, 1, 1) __launch_bounds__(256, 1)
k_gru_persist(const float* __restrict__ GI, float* __restrict__ HS,
              const float* __restrict__ whh, const float* __restrict__ bhh, int R)
{
    extern __shared__ float sm[];
    float* hbuf0 = sm;                       // [row*HPAD + k]
    float* hbuf1 = sm + RPS*HPAD;
    float2* wsm  = (float2*)(sm + 2*RPS*HPAD); // [(g*256+k)*16 + up]

    uint32_t rank;
    asm("mov.u32 %0, %%cluster_ctarank;" : "=r"(rank));
    int cid  = blockIdx.x >> 3;
    int dir  = cid & 1;
    int slab = cid >> 1;
    int r0   = slab * RPS;
    int u0   = (int)rank * UPC;

    int tid = threadIdx.x;
    int row = tid & 15;
    int up  = tid >> 4;
    int u   = u0 + up*2;

    // stage weights once: wsm[(g*256+k)*16+up] = {whh[.., u, k], whh[.., u+1, k]}
    for (int i = tid; i < 3*256*16; i += 256) {
        int g = i >> 12;
        int k = (i >> 4) & 255;
        int uu = i & 15;
        const float* wp = whh + ((size_t)(dir*768 + g*256 + u0 + uu*2))*256 + k;
        wsm[i] = make_float2(wp[0], wp[256]);
    }
    // zero h buffer 0
    for (int i = tid; i < RPS*HPAD; i += 256) hbuf0[i] = 0.f;

    // biases (persistent in regs)
    float br0 = bhh[dir*768 + u],        br1 = bhh[dir*768 + u + 1];
    float bz0 = bhh[dir*768 + 256 + u],  bz1 = bhh[dir*768 + 256 + u + 1];
    float bn0 = bhh[dir*768 + 512 + u],  bn1 = bhh[dir*768 + 512 + u + 1];

    // DSMEM addresses of both buffers in every peer
    uint32_t b0 = smem_u32(hbuf0), b1 = smem_u32(hbuf1);
    uint32_t p0[CSZ], p1[CSZ];
#pragma unroll
    for (int pr = 0; pr < CSZ; pr++) { p0[pr] = mapa_u32(b0, pr); p1[pr] = mapa_u32(b1, pr); }
    uint32_t xoff = (uint32_t)((row*HPAD + u) * 4);

    cluster_sync_();

    for (int s = 0; s < LSEQ; s++) {
        int t = dir ? (LSEQ-1-s) : s;
        const float* gip = GI + ((size_t)t*1536 + dir*768)*R + r0 + row;
        float gr0 = gip[(size_t)(u)      *R];
        float gr1 = gip[(size_t)(u+1)    *R];
        float gz0 = gip[(size_t)(256+u)  *R];
        float gz1 = gip[(size_t)(256+u+1)*R];
        float gn0 = gip[(size_t)(512+u)  *R];
        float gn1 = gip[(size_t)(512+u+1)*R];

        const float* hb = (s & 1) ? hbuf1 : hbuf0;
        const float* hrow = hb + row*HPAD;

        unsigned long long ar = 0, az = 0, an = 0;
#pragma unroll 8
        for (int k = 0; k < 256; k++) {
            unsigned long long h2 = pack2u(hrow[k]);
            ffma2u(ar, *(const unsigned long long*)&wsm[(       k)*16 + up], h2);
            ffma2u(az, *(const unsigned long long*)&wsm[( 256 + k)*16 + up], h2);
            ffma2u(an, *(const unsigned long long*)&wsm[( 512 + k)*16 + up], h2);
        }
        float2 AR = *(float2*)&ar, AZ = *(float2*)&az, AN = *(float2*)&an;
        float hp0 = hrow[u], hp1 = hrow[u+1];

        float rg0 = 1.f / (1.f + expf(-(gr0 + AR.x + br0)));
        float rg1 = 1.f / (1.f + expf(-(gr1 + AR.y + br1)));
        float zg0 = 1.f / (1.f + expf(-(gz0 + AZ.x + bz0)));
        float zg1 = 1.f / (1.f + expf(-(gz1 + AZ.y + bz1)));
        float ng0 = tanhf(gn0 + rg0 * (AN.x + bn0));
        float ng1 = tanhf(gn1 + rg1 * (AN.y + bn1));
        float h0 = (1.f - zg0) * ng0 + zg0 * hp0;
        float h1 = (1.f - zg1) * ng1 + zg1 * hp1;

        // global HS[t][dir][u][r]
        size_t hs = (((size_t)t*2 + dir)*HID + u)*R + r0 + row;
        HS[hs] = h0; HS[hs + R] = h1;

        // push slice into all peers' next buffer
        float2 hv = make_float2(h0, h1);
        const uint32_t* pp = (s & 1) ? p0 : p1;
#pragma unroll
        for (int pr = 0; pr < CSZ; pr++) st_cluster64(pp[pr] + xoff, hv);

        cluster_sync_();
    }
}

// ------------------- transpose HS[t][d][u][r] -> OUT[r][t][d*256+u] ---------
__global__ void k_trans(const float* __restrict__ HS, float* __restrict__ OUT, int R)
{
    int t = blockIdx.x, dd0 = blockIdx.y*32, r0 = blockIdx.z*32;
    __shared__ float tile[32][33];
    int tx = threadIdx.x, ty = threadIdx.y;
#pragma unroll
    for (int i = 0; i < 4; i++) {
        int uu = ty + 8*i;
        int dd = dd0 + uu; int d = dd >> 8, u = dd & 255;
        tile[uu][tx] = HS[(((size_t)t*2 + d)*256 + u)*R + r0 + tx];
    }
    __syncthreads();
#pragma unroll
    for (int i = 0; i < 4; i++) {
        int rr = ty + 8*i;
        OUT[((size_t)(r0+rr)*LSEQ + t)*LD + dd0 + tx] = tile[tx][rr];
    }
}

// ------------------- BiDAF pre ----------------------------------------------
__global__ void k_bidaf_pre(const float* __restrict__ Cseq, const float* __restrict__ Qseq,
                            const float* __restrict__ bw,
                            float* __restrict__ CW, float* __restrict__ QW,
                            float* __restrict__ CW2, int cdiv)
{
    int r = blockIdx.y;
    int i = blockIdx.x*8 + (threadIdx.x >> 5);
    int lane = threadIdx.x & 31;
    const float* c = Cseq + ((size_t)(r >> cdiv)*LSEQ + i)*LD;
    const float* q = Qseq + ((size_t)r*LSEQ + i)*LD;
    float sc = 0.f, sq = 0.f;
    for (int d = lane; d < LD; d += 32) {
        float cv = c[d];
        sc = fmaf(cv, bw[d], sc);
        sq = fmaf(q[d], bw[512 + d], sq);
        CW2[((size_t)r*LSEQ + i)*LD + d] = cv * bw[1024 + d];
    }
#pragma unroll
    for (int o = 16; o; o >>= 1) {
        sc += __shfl_xor_sync(0xffffffffu, sc, o);
        sq += __shfl_xor_sync(0xffffffffu, sq, o);
    }
    if (!lane) { CW[r*LSEQ + i] = sc; QW[r*LSEQ + i] = sq; }
}

// ------------------- softmax over j, capture row max -------------------------
__global__ void k_softmax(float* __restrict__ S, const float* __restrict__ CW,
                          const float* __restrict__ QW, const float* __restrict__ bb,
                          float* __restrict__ Mx)
{
    int r = blockIdx.y, i = blockIdx.x, j = threadIdx.x;
    float bsum = bb[0] + bb[1] + bb[2];
    float* row = S + ((size_t)r*LSEQ + i)*LSEQ;
    float v = row[j] + CW[r*LSEQ + i] + QW[r*LSEQ + j] + bsum;
    __shared__ float red[16];
    float m = v;
#pragma unroll
    for (int o = 16; o; o >>= 1) m = fmaxf(m, __shfl_xor_sync(0xffffffffu, m, o));
    if (!(j & 31)) red[j >> 5] = m;
    __syncthreads();
    float mm = red[0];
#pragma unroll
    for (int w = 1; w < 8; w++) mm = fmaxf(mm, red[w]);
    float e = expf(v - mm);
    float s = e;
#pragma unroll
    for (int o = 16; o; o >>= 1) s += __shfl_xor_sync(0xffffffffu, s, o);
    __syncthreads();
    if (!(j & 31)) red[8 + (j >> 5)] = s;
    __syncthreads();
    float ss = 0.f;
#pragma unroll
    for (int w = 0; w < 8; w++) ss += red[8 + w];
    row[j] = e / ss;
    if (j == 0) Mx[r*LSEQ + i] = mm;
}

// ------------------- q2c ------------------------------------------------------
__global__ void k_q2c(const float* __restrict__ Mx, const float* __restrict__ Cseq,
                      float* __restrict__ Q2C, int cdiv)
{
    int r = blockIdx.x, tid = threadIdx.x;
    __shared__ float red[8];
    __shared__ float bbv[256];
    float m = Mx[r*LSEQ + tid];
    float w = m;
#pragma unroll
    for (int o = 16; o; o >>= 1) w = fmaxf(w, __shfl_xor_sync(0xffffffffu, w, o));
    if (!(tid & 31)) red[tid >> 5] = w;
    __syncthreads();
    float mm = red[0];
#pragma unroll
    for (int i = 1; i < 8; i++) mm = fmaxf(mm, red[i]);
    float e = expf(m - mm);
    bbv[tid] = e;
    float s = e;
#pragma unroll
    for (int o = 16; o; o >>= 1) s += __shfl_xor_sync(0xffffffffu, s, o);
    __syncthreads();
    if (!(tid & 31)) red[tid >> 5] = s;
    __syncthreads();
    float ss = 0.f;
#pragma unroll
    for (int i = 0; i < 8; i++) ss += red[i];
    float inv = 1.f / ss;
    const float* cb = Cseq + (size_t)(r >> cdiv)*LSEQ*LD;
    for (int d = tid; d < LD; d += 256) {
        float acc = 0.f;
        for (int i = 0; i < 256; i++) acc = fmaf(bbv[i], cb[(size_t)i*LD + d], acc);
        Q2C[r*LD + d] = acc * inv;
    }
}

// ------------------- attention output assembly + relu ------------------------
__global__ void k_att(const float* __restrict__ Cseq, const float* __restrict__ C2Q,
                      const float* __restrict__ Q2C, float* __restrict__ ATT, int cdiv)
{
    int i = blockIdx.x, r = blockIdx.y, d = threadIdx.x;
    float cv  = Cseq[((size_t)(r >> cdiv)*LSEQ + i)*LD + d];
    float c2q = C2Q [((size_t)r*LSEQ + i)*LD + d];
    float q2c = Q2C [r*LD + d];
    float* o = ATT + ((size_t)i*NR2 + r)*F8;
    o[d]        = fmaxf(cv, 0.f);
    o[512 + d]  = fmaxf(c2q, 0.f);
    o[1024 + d] = fmaxf(cv * c2q, 0.f);
    o[1536 + d] = fmaxf(cv * q2c, 0.f);
}

// ------------------- final: max over k, dot rank_w (2-phase) ------------------
__global__ void k_final1(const float* __restrict__ A1, const float* __restrict__ A2,
                         const float* __restrict__ rw, float* __restrict__ part)
{
    int bo = blockIdx.x, tile = blockIdx.y, tid = threadIdx.x;
    int r0 = bo*2, r1 = r0 + 1;
    float acc = 0.f;
    for (int ii = 0; ii < 16; ii++) {
        int i = tile*16 + ii;
        size_t base0 = ((size_t)i*NR2 + r0)*F8;
        size_t base1 = ((size_t)i*NR2 + r1)*F8;
        const float4* a0 = (const float4*)(A1 + base0);
        const float4* a1 = (const float4*)(A1 + base1);
        const float4* b0 = (const float4*)(A2 + base0);
        const float4* b1 = (const float4*)(A2 + base1);
        const float4* w  = (const float4*)(rw + (size_t)i*F8);
#pragma unroll
        for (int f = tid; f < 512; f += 256) {
            float4 x0 = a0[f], x1 = a1[f], y0 = b0[f], y1 = b1[f], wv = w[f];
            acc = fmaf(wv.x, fmaxf(x0.x + y0.x, x1.x + y1.x), acc);
            acc = fmaf(wv.y, fmaxf(x0.y + y0.y, x1.y + y1.y), acc);
            acc = fmaf(wv.z, fmaxf(x0.z + y0.z, x1.z + y1.z), acc);
            acc = fmaf(wv.w, fmaxf(x0.w + y0.w, x1.w + y1.w), acc);
        }
    }
    __shared__ float red[8];
#pragma unroll
    for (int o = 16; o; o >>= 1) acc += __shfl_xor_sync(0xffffffffu, acc, o);
    if (!(tid & 31)) red[tid >> 5] = acc;
    __syncthreads();
    if (tid == 0) {
        float s = 0.f;
        for (int i = 0; i < 8; i++) s += red[i];
        part[bo*16 + tile] = s;
    }
}

__global__ void k_final2(const float* __restrict__ part, const float* __restrict__ rb,
                         float* __restrict__ out)
{
    int bo = threadIdx.x;
    float s = 0.f;
    for (int t = 0; t < 16; t++) s += part[bo*16 + t];
    out[bo] = s + rb[0];
}

// ------------------- host driver ---------------------------------------------
extern "C" void kernel_launch(void* const* d_in, const int* in_sizes, int n_in,
                              void* d_out, int out_size)
{
    const int*   q     = (const int*)d_in[0];
    const int*   a     = (const int*)d_in[1];
    const float* emb   = (const float*)d_in[2];
    const float* g1_wih = (const float*)d_in[3];
    const float* g1_whh = (const float*)d_in[4];
    const float* g1_bih = (const float*)d_in[5];
    const float* g1_bhh = (const float*)d_in[6];
    const float* g2_wih = (const float*)d_in[7];
    const float* g2_whh = (const float*)d_in[8];
    const float* g2_bih = (const float*)d_in[9];
    const float* g2_bhh = (const float*)d_in[10];
    const float* b1_w  = (const float*)d_in[11];
    const float* b1_b  = (const float*)d_in[12];
    const float* b2_w  = (const float*)d_in[13];
    const float* b2_b  = (const float*)d_in[14];
    const float* rank_w = (const float*)d_in[15];
    const float* rank_b = (const float*)d_in[16];
    float* out = (float*)d_out;

    float *X1, *GI1, *HS1, *CQ1, *CW2, *S, *CW, *QW, *Mx, *Q2C, *C2Q, *ATT, *GI2, *HS2, *C2, *AT2, *PART;
    cudaGetSymbolAddress((void**)&X1,  g_X1);
    cudaGetSymbolAddress((void**)&GI1, g_GI1);
    cudaGetSymbolAddress((void**)&HS1, g_HS1);
    cudaGetSymbolAddress((void**)&CQ1, g_CQ1);
    cudaGetSymbolAddress((void**)&CW2, g_CW2);
    cudaGetSymbolAddress((void**)&S,   g_S);
    cudaGetSymbolAddress((void**)&CW,  g_CW);
    cudaGetSymbolAddress((void**)&QW,  g_QW);
    cudaGetSymbolAddress((void**)&Mx,  g_M);
    cudaGetSymbolAddress((void**)&Q2C, g_Q2C);
    cudaGetSymbolAddress((void**)&C2Q, g_C2Q);
    cudaGetSymbolAddress((void**)&ATT, g_ATT);
    cudaGetSymbolAddress((void**)&GI2, g_GI2);
    cudaGetSymbolAddress((void**)&HS2, g_HS2);
    cudaGetSymbolAddress((void**)&C2,  g_C2);
    cudaGetSymbolAddress((void**)&AT2, g_AT2);
    cudaGetSymbolAddress((void**)&PART, g_PART);

    const int PSMEM = (2*RPS*HPAD)*4 + 3*256*16*8;   // 33024 + 98304 = 131328 B
    cudaFuncSetAttribute(k_gru_persist, cudaFuncAttributeMaxDynamicSharedMemorySize, PSMEM);

    // 1) embedding
    k_embed<<<dim3(LSEQ, NR1), 64>>>(q, a, emb);

    // 2) GI1 = Wih1 @ X1[t]^T (batched over t)
    k_gemm_nt<<<dim3(12, 2, LSEQ), 128>>>(g1_wih, X1, GI1, g1_bih,
                                          1536, NR1, VEC, 0, (long)NR1*VEC, (long)1536*NR1);
    // 3) BiGRU-1: persistent cluster kernel (12 clusters x 8 CTAs)
    k_gru_persist<<<96, 256, PSMEM>>>(GI1, HS1, g1_whh, g1_bhh, NR1);
    // 4) transpose to [seq][t][d]
    k_trans<<<dim3(LSEQ, 16, NR1/32), dim3(32, 8)>>>(HS1, CQ1, NR1);

    // 5) BiDAF-1 (c = question enc, q = article enc)
    const float* Qb1 = CQ1 + (size_t)32*LSEQ*LD;
    k_bidaf_pre<<<dim3(32, NR2), 256>>>(CQ1, Qb1, b1_w, CW, QW, CW2, 1);
    k_gemm_nt<<<dim3(2, 4, NR2), 128>>>(CW2, Qb1, S, nullptr,
                                        256, 256, 512, (long)LSEQ*LD, (long)LSEQ*LD, (long)LSEQ*LSEQ);
    k_softmax<<<dim3(LSEQ, NR2), 256>>>(S, CW, QW, b1_b, Mx);
    k_q2c<<<NR2, 256>>>(Mx, CQ1, Q2C, 1);
    k_gemm_nn<<<dim3(2, 8, NR2), 128>>>(S, Qb1, C2Q,
                                        256, 512, 256, (long)LSEQ*LSEQ, (long)LSEQ*LD, (long)LSEQ*LD);
    k_att<<<dim3(LSEQ, NR2), 512>>>(CQ1, C2Q, Q2C, ATT, 1);

    // 6) GI2 = Wih2 @ ATT[t]^T (batched over t)
    k_gemm_nt<<<dim3(12, 1, LSEQ), 128>>>(g2_wih, ATT, GI2, g2_bih,
                                          1536, NR2, F8, 0, (long)NR2*F8, (long)1536*NR2);
    // 7) BiGRU-2: persistent cluster kernel (8 clusters x 8 CTAs)
    k_gru_persist<<<64, 256, PSMEM>>>(GI2, HS2, g2_whh, g2_bhh, NR2);
    k_trans<<<dim3(LSEQ, 16, NR2/32), dim3(32, 8)>>>(HS2, C2, NR2);

    // 8) BiDAF-2 (self)
    k_bidaf_pre<<<dim3(32, NR2), 256>>>(C2, C2, b2_w, CW, QW, CW2, 0);
    k_gemm_nt<<<dim3(2, 4, NR2), 128>>>(CW2, C2, S, nullptr,
                                        256, 256, 512, (long)LSEQ*LD, (long)LSEQ*LD, (long)LSEQ*LSEQ);
    k_softmax<<<dim3(LSEQ, NR2), 256>>>(S, CW, QW, b2_b, Mx);
    k_q2c<<<NR2, 256>>>(Mx, C2, Q2C, 0);
    k_gemm_nn<<<dim3(2, 8, NR2), 128>>>(S, C2, C2Q,
                                        256, 512, 256, (long)LSEQ*LSEQ, (long)LSEQ*LD, (long)LSEQ*LD);
    k_att<<<dim3(LSEQ, NR2), 512>>>(C2, C2Q, Q2C, AT2, 0);

    // 9) final
    k_final1<<<dim3(32, 16), 256>>>(ATT, AT2, rank_w, PART);
    k_final2<<<1, 32>>>(PART, rank_b, out);
}

// round 11
// speedup vs baseline: 2.5768x; 1.4468x over previous
#include <cuda_runtime.h>
#include <math.h>
#include <stdint.h>

#define LSEQ 256
#define VEC  256
#define HID  256
#define NR1  96      // 32 question seqs + 64 article seqs
#define NR2  64      // Beff rows
#define LD   512     // 2*HID
#define F8   2048

#define RPS   16     // rows per slab (per cluster)
#define UPC   32     // units per CTA
#define CSZ   8      // cluster size
#define HPAD  258    // padded row stride (floats) in h buffer

// ------------------- scratch (device globals; no allocs) -------------------
__device__ __align__(256) float g_X1 [LSEQ*NR1*VEC];
__device__ __align__(256) float g_GI1[LSEQ*1536*NR1];
__device__ __align__(256) float g_HS1[LSEQ*2*HID*NR1];
__device__ __align__(256) float g_CQ1[NR1*LSEQ*LD];
__device__ __align__(256) float g_CW2[NR2*LSEQ*LD];
__device__ __align__(256) float g_S  [NR2*LSEQ*LSEQ];
__device__ __align__(256) float g_CW [NR2*LSEQ];
__device__ __align__(256) float g_QW [NR2*LSEQ];
__device__ __align__(256) float g_M  [NR2*LSEQ];
__device__ __align__(256) float g_Q2C[NR2*LD];
__device__ __align__(256) float g_C2Q[NR2*LSEQ*LD];
__device__ __align__(256) float g_ATT[LSEQ*NR2*F8];
__device__ __align__(256) float g_GI2[LSEQ*1536*NR2];
__device__ __align__(256) float g_HS2[LSEQ*2*HID*NR2];
__device__ __align__(256) float g_C2 [NR2*LSEQ*LD];
__device__ __align__(256) float g_AT2[LSEQ*NR2*F8];
__device__ __align__(256) float g_PART[32*16];

// ------------------- packed fp32x2 helpers ---------------------------------
__device__ __forceinline__ void ffma2u(unsigned long long& acc,
                                       unsigned long long a, unsigned long long b) {
    asm("fma.rn.f32x2 %0, %1, %2, %0;" : "+l"(acc) : "l"(a), "l"(b));
}
__device__ __forceinline__ unsigned long long pack2u(float w) {
    unsigned long long r;
    asm("mov.b64 %0, {%1, %1};" : "=l"(r) : "f"(w));
    return r;
}

// ------------------- tf32 tensor-core helpers --------------------------------
__device__ __forceinline__ uint32_t f2tf32(float x) {
    uint32_t r; asm("cvt.rna.tf32.f32 %0, %1;" : "=r"(r) : "f"(x)); return r;
}
__device__ __forceinline__ void mma_tf32(float* c, const uint32_t* a,
                                         uint32_t b0, uint32_t b1) {
    asm volatile("mma.sync.aligned.m16n8k8.row.col.f32.tf32.tf32.f32 "
        "{%0,%1,%2,%3}, {%4,%5,%6,%7}, {%8,%9}, {%0,%1,%2,%3};"
        : "+f"(c[0]), "+f"(c[1]), "+f"(c[2]), "+f"(c[3])
        : "r"(a[0]), "r"(a[1]), "r"(a[2]), "r"(a[3]), "r"(b0), "r"(b1));
}

// ------------------- cluster helpers ----------------------------------------
__device__ __forceinline__ uint32_t smem_u32(const void* p) {
    return (uint32_t)__cvta_generic_to_shared(p);
}
__device__ __forceinline__ uint32_t mapa_u32(uint32_t addr, uint32_t rank) {
    uint32_t r;
    asm("mapa.shared::cluster.u32 %0, %1, %2;" : "=r"(r) : "r"(addr), "r"(rank));
    return r;
}
__device__ __forceinline__ void st_cluster64(uint32_t addr, float2 v) {
    asm volatile("st.shared::cluster.b64 [%0], %1;"
                 :: "r"(addr), "l"(*(unsigned long long*)&v) : "memory");
}
__device__ __forceinline__ void cluster_sync_() {
    asm volatile("barrier.cluster.arrive.aligned;" ::: "memory");
    asm volatile("barrier.cluster.wait.aligned;" ::: "memory");
}

// ------------------- embedding gather ---------------------------------------
__global__ void k_embed(const int* __restrict__ q, const int* __restrict__ a,
                        const float* __restrict__ emb)
{
    int t = blockIdx.x, r = blockIdx.y;
    int tok = (r < 32) ? q[r*LSEQ + t] : a[(r-32)*LSEQ + t];
    const float4* src = (const float4*)(emb + (size_t)tok*VEC);
    float4* dst = (float4*)(g_X1 + ((size_t)t*NR1 + r)*VEC);
    dst[threadIdx.x] = src[threadIdx.x];
}

// ------------------- tf32 TC GEMM NT: C[m][n]=sum_k A[m][k]*B[n][k] (+bias) --
// BM=128, BN=64, BK=32, 256 threads = 8 warps (4m x 2n), warp tile 32x32.
// M%128==0, K%32==0; N guarded (N multiple of 2).
__global__ __launch_bounds__(256) void k_tc_nt(
    const float* __restrict__ A, const float* __restrict__ B,
    float* __restrict__ C, const float* __restrict__ bias,
    int M, int N, int K, long sA, long sB, long sC)
{
    __shared__ uint32_t As[128][36];
    __shared__ uint32_t Bs[64][36];
    const float* Ab = A + (size_t)blockIdx.z * sA;
    const float* Bb = B + (size_t)blockIdx.z * sB;
    float* Cb = C + (size_t)blockIdx.z * sC;
    int m0 = blockIdx.x*128, n0 = blockIdx.y*64;
    int tid = threadIdx.x, lane = tid & 31;
    int wm = ((tid>>5) & 3)*32, wn = (tid>>7)*32;
    int g = lane>>2, tg = lane&3;
    int am = tid>>3, ac = tid&7;

    float4 ra[4], rb[2];
    float acc[2][4][4];
#pragma unroll
    for (int i=0;i<2;i++)
#pragma unroll
        for (int j=0;j<4;j++)
#pragma unroll
            for (int l=0;l<4;l++) acc[i][j][l]=0.f;

    auto LDG = [&](int k0) {
#pragma unroll
        for (int p=0;p<4;p++)
            ra[p] = *(const float4*)(Ab + (size_t)(m0+am+32*p)*K + k0 + ac*4);
#pragma unroll
        for (int p=0;p<2;p++) {
            int n = n0 + am + 32*p;
            rb[p] = (n < N) ? *(const float4*)(Bb + (size_t)n*K + k0 + ac*4)
                            : make_float4(0.f,0.f,0.f,0.f);
        }
    };
    auto STS = [&]() {
#pragma unroll
        for (int p=0;p<4;p++) {
            uint4 v = {f2tf32(ra[p].x),f2tf32(ra[p].y),f2tf32(ra[p].z),f2tf32(ra[p].w)};
            *(uint4*)&As[am+32*p][ac*4] = v;
        }
#pragma unroll
        for (int p=0;p<2;p++) {
            uint4 v = {f2tf32(rb[p].x),f2tf32(rb[p].y),f2tf32(rb[p].z),f2tf32(rb[p].w)};
            *(uint4*)&Bs[am+32*p][ac*4] = v;
        }
    };
    auto COMPUTE = [&]() {
#pragma unroll
        for (int ks=0;ks<4;ks++) {
            uint32_t a[2][4];
#pragma unroll
            for (int mi=0;mi<2;mi++) {
                int r = wm + mi*16 + g, c = ks*8 + tg;
                a[mi][0]=As[r][c];   a[mi][1]=As[r+8][c];
                a[mi][2]=As[r][c+4]; a[mi][3]=As[r+8][c+4];
            }
#pragma unroll
            for (int ni=0;ni<4;ni++) {
                int bn = wn + ni*8 + g, bk = ks*8 + tg;
                uint32_t b0=Bs[bn][bk], b1=Bs[bn][bk+4];
                mma_tf32(acc[0][ni], a[0], b0, b1);
                mma_tf32(acc[1][ni], a[1], b0, b1);
            }
        }
    };

    LDG(0); STS(); __syncthreads();
    for (int k0 = 32; k0 < K; k0 += 32) {
        LDG(k0);
        COMPUTE();
        __syncthreads();
        STS();
        __syncthreads();
    }
    COMPUTE();

#pragma unroll
    for (int mi=0;mi<2;mi++) {
        int row = m0 + wm + mi*16 + g;
        float b0v = bias ? bias[row]   : 0.f;
        float b8v = bias ? bias[row+8] : 0.f;
#pragma unroll
        for (int ni=0;ni<4;ni++) {
            int col = n0 + wn + ni*8 + tg*2;
            if (col < N) {
                float2 v0 = {acc[mi][ni][0] + b0v, acc[mi][ni][1] + b0v};
                float2 v1 = {acc[mi][ni][2] + b8v, acc[mi][ni][3] + b8v};
                *(float2*)(Cb + (size_t)row*N + col) = v0;
                *(float2*)(Cb + (size_t)(row+8)*N + col) = v1;
            }
        }
    }
}

// ------------------- tf32 TC GEMM NN: C[m][n]=sum_k A[m][k]*B[k][n] ----------
// BM=128, BN=64, BK=32. M%128==0, N%64==0, K%32==0.
__global__ __launch_bounds__(256) void k_tc_nn(
    const float* __restrict__ A, const float* __restrict__ B,
    float* __restrict__ C,
    int M, int N, int K, long sA, long sB, long sC)
{
    __shared__ uint32_t As[128][36];
    __shared__ uint32_t Bs[32][72];
    const float* Ab = A + (size_t)blockIdx.z * sA;
    const float* Bb = B + (size_t)blockIdx.z * sB;
    float* Cb = C + (size_t)blockIdx.z * sC;
    int m0 = blockIdx.x*128, n0 = blockIdx.y*64;
    int tid = threadIdx.x, lane = tid & 31;
    int wm = ((tid>>5) & 3)*32, wn = (tid>>7)*32;
    int g = lane>>2, tg = lane&3;
    int am = tid>>3, ac = tid&7;
    int bk = tid>>4, bc = tid&15;

    float4 ra[4], rb[2];
    float acc[2][4][4];
#pragma unroll
    for (int i=0;i<2;i++)
#pragma unroll
        for (int j=0;j<4;j++)
#pragma unroll
            for (int l=0;l<4;l++) acc[i][j][l]=0.f;

    auto LDG = [&](int k0) {
#pragma unroll
        for (int p=0;p<4;p++)
            ra[p] = *(const float4*)(Ab + (size_t)(m0+am+32*p)*K + k0 + ac*4);
#pragma unroll
        for (int p=0;p<2;p++)
            rb[p] = *(const float4*)(Bb + (size_t)(k0+bk+16*p)*N + n0 + bc*4);
    };
    auto STS = [&]() {
#pragma unroll
        for (int p=0;p<4;p++) {
            uint4 v = {f2tf32(ra[p].x),f2tf32(ra[p].y),f2tf32(ra[p].z),f2tf32(ra[p].w)};
            *(uint4*)&As[am+32*p][ac*4] = v;
        }
#pragma unroll
        for (int p=0;p<2;p++) {
            uint4 v = {f2tf32(rb[p].x),f2tf32(rb[p].y),f2tf32(rb[p].z),f2tf32(rb[p].w)};
            *(uint4*)&Bs[bk+16*p][bc*4] = v;
        }
    };
    auto COMPUTE = [&]() {
#pragma unroll
        for (int ks=0;ks<4;ks++) {
            uint32_t a[2][4];
#pragma unroll
            for (int mi=0;mi<2;mi++) {
                int r = wm + mi*16 + g, c = ks*8 + tg;
                a[mi][0]=As[r][c];   a[mi][1]=As[r+8][c];
                a[mi][2]=As[r][c+4]; a[mi][3]=As[r+8][c+4];
            }
#pragma unroll
            for (int ni=0;ni<4;ni++) {
                int bn = wn + ni*8 + g;
                uint32_t b0=Bs[ks*8+tg][bn], b1=Bs[ks*8+tg+4][bn];
                mma_tf32(acc[0][ni], a[0], b0, b1);
                mma_tf32(acc[1][ni], a[1], b0, b1);
            }
        }
    };

    LDG(0); STS(); __syncthreads();
    for (int k0 = 32; k0 < K; k0 += 32) {
        LDG(k0);
        COMPUTE();
        __syncthreads();
        STS();
        __syncthreads();
    }
    COMPUTE();

#pragma unroll
    for (int mi=0;mi<2;mi++) {
        int row = m0 + wm + mi*16 + g;
#pragma unroll
        for (int ni=0;ni<4;ni++) {
            int col = n0 + wn + ni*8 + tg*2;
            float2 v0 = {acc[mi][ni][0], acc[mi][ni][1]};
            float2 v1 = {acc[mi][ni][2], acc[mi][ni][3]};
            *(float2*)(Cb + (size_t)row*N + col) = v0;
            *(float2*)(Cb + (size_t)(row+8)*N + col) = v1;
        }
    }
}

// ------------------- persistent cluster GRU ---------------------------------
__global__ void __cluster_dims__(CSZ, 1, 1) __launch_bounds__(256, 1)
k_gru_persist(const float* __restrict__ GI, float* __restrict__ HS,
              const float* __restrict__ whh, const float* __restrict__ bhh, int R)
{
    extern __shared__ float sm[];
    float* hbuf0 = sm;                         // [row*HPAD + k]
    float* hbuf1 = sm + RPS*HPAD;
    float2* wsm  = (float2*)(sm + 2*RPS*HPAD); // [(g*256+k)*16 + up]

    uint32_t rank;
    asm("mov.u32 %0, %%cluster_ctarank;" : "=r"(rank));
    int cid  = blockIdx.x >> 3;
    int dir  = cid & 1;
    int slab = cid >> 1;
    int r0   = slab * RPS;
    int u0   = (int)rank * UPC;

    int tid = threadIdx.x;
    int row = tid & 15;
    int up  = tid >> 4;
    int u   = u0 + up*2;

    for (int i = tid; i < 3*256*16; i += 256) {
        int g = i >> 12;
        int k = (i >> 4) & 255;
        int uu = i & 15;
        const float* wp = whh + ((size_t)(dir*768 + g*256 + u0 + uu*2))*256 + k;
        wsm[i] = make_float2(wp[0], wp[256]);
    }
    for (int i = tid; i < RPS*HPAD; i += 256) hbuf0[i] = 0.f;

    float br0 = bhh[dir*768 + u],        br1 = bhh[dir*768 + u + 1];
    float bz0 = bhh[dir*768 + 256 + u],  bz1 = bhh[dir*768 + 256 + u + 1];
    float bn0 = bhh[dir*768 + 512 + u],  bn1 = bhh[dir*768 + 512 + u + 1];

    uint32_t b0 = smem_u32(hbuf0), b1 = smem_u32(hbuf1);
    uint32_t p0[CSZ], p1[CSZ];
#pragma unroll
    for (int pr = 0; pr < CSZ; pr++) { p0[pr] = mapa_u32(b0, pr); p1[pr] = mapa_u32(b1, pr); }
    uint32_t xoff = (uint32_t)((row*HPAD + u) * 4);

    cluster_sync_();

    for (int s = 0; s < LSEQ; s++) {
        int t = dir ? (LSEQ-1-s) : s;
        const float* gip = GI + ((size_t)t*1536 + dir*768)*R + r0 + row;
        float gr0 = gip[(size_t)(u)      *R];
        float gr1 = gip[(size_t)(u+1)    *R];
        float gz0 = gip[(size_t)(256+u)  *R];
        float gz1 = gip[(size_t)(256+u+1)*R];
        float gn0 = gip[(size_t)(512+u)  *R];
        float gn1 = gip[(size_t)(512+u+1)*R];

        const float* hb = (s & 1) ? hbuf1 : hbuf0;
        const float* hrow = hb + row*HPAD;

        unsigned long long ar = 0, az = 0, an = 0;
#pragma unroll 8
        for (int k = 0; k < 256; k++) {
            unsigned long long h2 = pack2u(hrow[k]);
            ffma2u(ar, *(const unsigned long long*)&wsm[(       k)*16 + up], h2);
            ffma2u(az, *(const unsigned long long*)&wsm[( 256 + k)*16 + up], h2);
            ffma2u(an, *(const unsigned long long*)&wsm[( 512 + k)*16 + up], h2);
        }
        float2 AR = *(float2*)&ar, AZ = *(float2*)&az, AN = *(float2*)&an;
        float hp0 = hrow[u], hp1 = hrow[u+1];

        float rg0 = 1.f / (1.f + expf(-(gr0 + AR.x + br0)));
        float rg1 = 1.f / (1.f + expf(-(gr1 + AR.y + br1)));
        float zg0 = 1.f / (1.f + expf(-(gz0 + AZ.x + bz0)));
        float zg1 = 1.f / (1.f + expf(-(gz1 + AZ.y + bz1)));
        float ng0 = tanhf(gn0 + rg0 * (AN.x + bn0));
        float ng1 = tanhf(gn1 + rg1 * (AN.y + bn1));
        float h0 = (1.f - zg0) * ng0 + zg0 * hp0;
        float h1 = (1.f - zg1) * ng1 + zg1 * hp1;

        size_t hs = (((size_t)t*2 + dir)*HID + u)*R + r0 + row;
        HS[hs] = h0; HS[hs + R] = h1;

        float2 hv = make_float2(h0, h1);
        const uint32_t* pp = (s & 1) ? p0 : p1;
#pragma unroll
        for (int pr = 0; pr < CSZ; pr++) st_cluster64(pp[pr] + xoff, hv);

        cluster_sync_();
    }
}

// ------------------- transpose HS[t][d][u][r] -> OUT[r][t][d*256+u] ---------
__global__ void k_trans(const float* __restrict__ HS, float* __restrict__ OUT, int R)
{
    int t = blockIdx.x, dd0 = blockIdx.y*32, r0 = blockIdx.z*32;
    __shared__ float tile[32][33];
    int tx = threadIdx.x, ty = threadIdx.y;
#pragma unroll
    for (int i = 0; i < 4; i++) {
        int uu = ty + 8*i;
        int dd = dd0 + uu; int d = dd >> 8, u = dd & 255;
        tile[uu][tx] = HS[(((size_t)t*2 + d)*256 + u)*R + r0 + tx];
    }
    __syncthreads();
#pragma unroll
    for (int i = 0; i < 4; i++) {
        int rr = ty + 8*i;
        OUT[((size_t)(r0+rr)*LSEQ + t)*LD + dd0 + tx] = tile[tx][rr];
    }
}

// ------------------- BiDAF pre ----------------------------------------------
__global__ void k_bidaf_pre(const float* __restrict__ Cseq, const float* __restrict__ Qseq,
                            const float* __restrict__ bw,
                            float* __restrict__ CW, float* __restrict__ QW,
                            float* __restrict__ CW2, int cdiv)
{
    int r = blockIdx.y;
    int i = blockIdx.x*8 + (threadIdx.x >> 5);
    int lane = threadIdx.x & 31;
    const float* c = Cseq + ((size_t)(r >> cdiv)*LSEQ + i)*LD;
    const float* q = Qseq + ((size_t)r*LSEQ + i)*LD;
    float sc = 0.f, sq = 0.f;
    for (int d = lane; d < LD; d += 32) {
        float cv = c[d];
        sc = fmaf(cv, bw[d], sc);
        sq = fmaf(q[d], bw[512 + d], sq);
        CW2[((size_t)r*LSEQ + i)*LD + d] = cv * bw[1024 + d];
    }
#pragma unroll
    for (int o = 16; o; o >>= 1) {
        sc += __shfl_xor_sync(0xffffffffu, sc, o);
        sq += __shfl_xor_sync(0xffffffffu, sq, o);
    }
    if (!lane) { CW[r*LSEQ + i] = sc; QW[r*LSEQ + i] = sq; }
}

// ------------------- softmax over j, capture row max -------------------------
__global__ void k_softmax(float* __restrict__ S, const float* __restrict__ CW,
                          const float* __restrict__ QW, const float* __restrict__ bb,
                          float* __restrict__ Mx)
{
    int r = blockIdx.y, i = blockIdx.x, j = threadIdx.x;
    float bsum = bb[0] + bb[1] + bb[2];
    float* row = S + ((size_t)r*LSEQ + i)*LSEQ;
    float v = row[j] + CW[r*LSEQ + i] + QW[r*LSEQ + j] + bsum;
    __shared__ float red[16];
    float m = v;
#pragma unroll
    for (int o = 16; o; o >>= 1) m = fmaxf(m, __shfl_xor_sync(0xffffffffu, m, o));
    if (!(j & 31)) red[j >> 5] = m;
    __syncthreads();
    float mm = red[0];
#pragma unroll
    for (int w = 1; w < 8; w++) mm = fmaxf(mm, red[w]);
    float e = expf(v - mm);
    float s = e;
#pragma unroll
    for (int o = 16; o; o >>= 1) s += __shfl_xor_sync(0xffffffffu, s, o);
    __syncthreads();
    if (!(j & 31)) red[8 + (j >> 5)] = s;
    __syncthreads();
    float ss = 0.f;
#pragma unroll
    for (int w = 0; w < 8; w++) ss += red[8 + w];
    row[j] = e / ss;
    if (j == 0) Mx[r*LSEQ + i] = mm;
}

// ------------------- q2c ------------------------------------------------------
__global__ void k_q2c(const float* __restrict__ Mx, const float* __restrict__ Cseq,
                      float* __restrict__ Q2C, int cdiv)
{
    int r = blockIdx.x, tid = threadIdx.x;
    __shared__ float red[8];
    __shared__ float bbv[256];
    float m = Mx[r*LSEQ + tid];
    float w = m;
#pragma unroll
    for (int o = 16; o; o >>= 1) w = fmaxf(w, __shfl_xor_sync(0xffffffffu, w, o));
    if (!(tid & 31)) red[tid >> 5] = w;
    __syncthreads();
    float mm = red[0];
#pragma unroll
    for (int i = 1; i < 8; i++) mm = fmaxf(mm, red[i]);
    float e = expf(m - mm);
    bbv[tid] = e;
    float s = e;
#pragma unroll
    for (int o = 16; o; o >>= 1) s += __shfl_xor_sync(0xffffffffu, s, o);
    __syncthreads();
    if (!(tid & 31)) red[tid >> 5] = s;
    __syncthreads();
    float ss = 0.f;
#pragma unroll
    for (int i = 0; i < 8; i++) ss += red[i];
    float inv = 1.f / ss;
    const float* cb = Cseq + (size_t)(r >> cdiv)*LSEQ*LD;
    for (int d = tid; d < LD; d += 256) {
        float acc = 0.f;
        for (int i = 0; i < 256; i++) acc = fmaf(bbv[i], cb[(size_t)i*LD + d], acc);
        Q2C[r*LD + d] = acc * inv;
    }
}

// ------------------- attention output assembly + relu ------------------------
__global__ void k_att(const float* __restrict__ Cseq, const float* __restrict__ C2Q,
                      const float* __restrict__ Q2C, float* __restrict__ ATT, int cdiv)
{
    int i = blockIdx.x, r = blockIdx.y, d = threadIdx.x;
    float cv  = Cseq[((size_t)(r >> cdiv)*LSEQ + i)*LD + d];
    float c2q = C2Q [((size_t)r*LSEQ + i)*LD + d];
    float q2c = Q2C [r*LD + d];
    float* o = ATT + ((size_t)i*NR2 + r)*F8;
    o[d]        = fmaxf(cv, 0.f);
    o[512 + d]  = fmaxf(c2q, 0.f);
    o[1024 + d] = fmaxf(cv * c2q, 0.f);
    o[1536 + d] = fmaxf(cv * q2c, 0.f);
}

// ------------------- final: max over k, dot rank_w (2-phase) ------------------
__global__ void k_final1(const float* __restrict__ A1, const float* __restrict__ A2,
                         const float* __restrict__ rw, float* __restrict__ part)
{
    int bo = blockIdx.x, tile = blockIdx.y, tid = threadIdx.x;
    int r0 = bo*2, r1 = r0 + 1;
    float acc = 0.f;
    for (int ii = 0; ii < 16; ii++) {
        int i = tile*16 + ii;
        size_t base0 = ((size_t)i*NR2 + r0)*F8;
        size_t base1 = ((size_t)i*NR2 + r1)*F8;
        const float4* a0 = (const float4*)(A1 + base0);
        const float4* a1 = (const float4*)(A1 + base1);
        const float4* b0 = (const float4*)(A2 + base0);
        const float4* b1 = (const float4*)(A2 + base1);
        const float4* w  = (const float4*)(rw + (size_t)i*F8);
#pragma unroll
        for (int f = tid; f < 512; f += 256) {
            float4 x0 = a0[f], x1 = a1[f], y0 = b0[f], y1 = b1[f], wv = w[f];
            acc = fmaf(wv.x, fmaxf(x0.x + y0.x, x1.x + y1.x), acc);
            acc = fmaf(wv.y, fmaxf(x0.y + y0.y, x1.y + y1.y), acc);
            acc = fmaf(wv.z, fmaxf(x0.z + y0.z, x1.z + y1.z), acc);
            acc = fmaf(wv.w, fmaxf(x0.w + y0.w, x1.w + y1.w), acc);
        }
    }
    __shared__ float red[8];
#pragma unroll
    for (int o = 16; o; o >>= 1) acc += __shfl_xor_sync(0xffffffffu, acc, o);
    if (!(tid & 31)) red[tid >> 5] = acc;
    __syncthreads();
    if (tid == 0) {
        float s = 0.f;
        for (int i = 0; i < 8; i++) s += red[i];
        part[bo*16 + tile] = s;
    }
}

__global__ void k_final2(const float* __restrict__ part, const float* __restrict__ rb,
                         float* __restrict__ out)
{
    int bo = threadIdx.x;
    float s = 0.f;
    for (int t = 0; t < 16; t++) s += part[bo*16 + t];
    out[bo] = s + rb[0];
}

// ------------------- host driver ---------------------------------------------
extern "C" void kernel_launch(void* const* d_in, const int* in_sizes, int n_in,
                              void* d_out, int out_size)
{
    const int*   q     = (const int*)d_in[0];
    const int*   a     = (const int*)d_in[1];
    const float* emb   = (const float*)d_in[2];
    const float* g1_wih = (const float*)d_in[3];
    const float* g1_whh = (const float*)d_in[4];
    const float* g1_bih = (const float*)d_in[5];
    const float* g1_bhh = (const float*)d_in[6];
    const float* g2_wih = (const float*)d_in[7];
    const float* g2_whh = (const float*)d_in[8];
    const float* g2_bih = (const float*)d_in[9];
    const float* g2_bhh = (const float*)d_in[10];
    const float* b1_w  = (const float*)d_in[11];
    const float* b1_b  = (const float*)d_in[12];
    const float* b2_w  = (const float*)d_in[13];
    const float* b2_b  = (const float*)d_in[14];
    const float* rank_w = (const float*)d_in[15];
    const float* rank_b = (const float*)d_in[16];
    float* out = (float*)d_out;

    float *X1, *GI1, *HS1, *CQ1, *CW2, *S, *CW, *QW, *Mx, *Q2C, *C2Q, *ATT, *GI2, *HS2, *C2, *AT2, *PART;
    cudaGetSymbolAddress((void**)&X1,  g_X1);
    cudaGetSymbolAddress((void**)&GI1, g_GI1);
    cudaGetSymbolAddress((void**)&HS1, g_HS1);
    cudaGetSymbolAddress((void**)&CQ1, g_CQ1);
    cudaGetSymbolAddress((void**)&CW2, g_CW2);
    cudaGetSymbolAddress((void**)&S,   g_S);
    cudaGetSymbolAddress((void**)&CW,  g_CW);
    cudaGetSymbolAddress((void**)&QW,  g_QW);
    cudaGetSymbolAddress((void**)&Mx,  g_M);
    cudaGetSymbolAddress((void**)&Q2C, g_Q2C);
    cudaGetSymbolAddress((void**)&C2Q, g_C2Q);
    cudaGetSymbolAddress((void**)&ATT, g_ATT);
    cudaGetSymbolAddress((void**)&GI2, g_GI2);
    cudaGetSymbolAddress((void**)&HS2, g_HS2);
    cudaGetSymbolAddress((void**)&C2,  g_C2);
    cudaGetSymbolAddress((void**)&AT2, g_AT2);
    cudaGetSymbolAddress((void**)&PART, g_PART);

    const int PSMEM = (2*RPS*HPAD)*4 + 3*256*16*8;   // 131328 B
    cudaFuncSetAttribute(k_gru_persist, cudaFuncAttributeMaxDynamicSharedMemorySize, PSMEM);

    // 1) embedding
    k_embed<<<dim3(LSEQ, NR1), 64>>>(q, a, emb);

    // 2) GI1 = Wih1 @ X1[t]^T (tf32 TC, batched over t)
    k_tc_nt<<<dim3(12, 2, LSEQ), 256>>>(g1_wih, X1, GI1, g1_bih,
                                        1536, NR1, VEC, 0, (long)NR1*VEC, (long)1536*NR1);
    // 3) BiGRU-1: persistent cluster kernel
    k_gru_persist<<<96, 256, PSMEM>>>(GI1, HS1, g1_whh, g1_bhh, NR1);
    // 4) transpose to [seq][t][d]
    k_trans<<<dim3(LSEQ, 16, NR1/32), dim3(32, 8)>>>(HS1, CQ1, NR1);

    // 5) BiDAF-1 (c = question enc, q = article enc)
    const float* Qb1 = CQ1 + (size_t)32*LSEQ*LD;
    k_bidaf_pre<<<dim3(32, NR2), 256>>>(CQ1, Qb1, b1_w, CW, QW, CW2, 1);
    k_tc_nt<<<dim3(2, 4, NR2), 256>>>(CW2, Qb1, S, nullptr,
                                      256, 256, 512, (long)LSEQ*LD, (long)LSEQ*LD, (long)LSEQ*LSEQ);
    k_softmax<<<dim3(LSEQ, NR2), 256>>>(S, CW, QW, b1_b, Mx);
    k_q2c<<<NR2, 256>>>(Mx, CQ1, Q2C, 1);
    k_tc_nn<<<dim3(2, 8, NR2), 256>>>(S, Qb1, C2Q,
                                      256, 512, 256, (long)LSEQ*LSEQ, (long)LSEQ*LD, (long)LSEQ*LD);
    k_att<<<dim3(LSEQ, NR2), 512>>>(CQ1, C2Q, Q2C, ATT, 1);

    // 6) GI2 = Wih2 @ ATT[t]^T (tf32 TC, batched over t)
    k_tc_nt<<<dim3(12, 1, LSEQ), 256>>>(g2_wih, ATT, GI2, g2_bih,
                                        1536, NR2, F8, 0, (long)NR2*F8, (long)1536*NR2);
    // 7) BiGRU-2
    k_gru_persist<<<64, 256, PSMEM>>>(GI2, HS2, g2_whh, g2_bhh, NR2);
    k_trans<<<dim3(LSEQ, 16, NR2/32), dim3(32, 8)>>>(HS2, C2, NR2);

    // 8) BiDAF-2 (self)
    k_bidaf_pre<<<dim3(32, NR2), 256>>>(C2, C2, b2_w, CW, QW, CW2, 0);
    k_tc_nt<<<dim3(2, 4, NR2), 256>>>(CW2, C2, S, nullptr,
                                      256, 256, 512, (long)LSEQ*LD, (long)LSEQ*LD, (long)LSEQ*LSEQ);
    k_softmax<<<dim3(LSEQ, NR2), 256>>>(S, CW, QW, b2_b, Mx);
    k_q2c<<<NR2, 256>>>(Mx, C2, Q2C, 0);
    k_tc_nn<<<dim3(2, 8, NR2), 256>>>(S, C2, C2Q,
                                      256, 512, 256, (long)LSEQ*LSEQ, (long)LSEQ*LD, (long)LSEQ*LD);
    k_att<<<dim3(LSEQ, NR2), 512>>>(C2, C2Q, Q2C, AT2, 0);

    // 9) final
    k_final1<<<dim3(32, 16), 256>>>(ATT, AT2, rank_w, PART);
    k_final2<<<1, 32>>>(PART, rank_b, out);
}